// round 6
// baseline (speedup 1.0000x reference)
#include <cuda_runtime.h>

#define N_NODES 100000
#define N_EDGES 1600000
#define E_TOT   (N_EDGES + N_NODES)
#define N_GRAPHS 64
#define NEG_SLOPE 0.2f
#define NEG_BIG  -1e30f
#define SCAN_BLK 1024
#define N_SBLK   ((N_NODES + SCAN_BLK - 1) / SCAN_BLK)   // 98
#define CAP1     100     // layer-1 per-warp slot capacity
#define CAP2     64      // layer-2 per-warp slot capacity
#define SWS      68      // padded head stride for s_w (bank-conflict-free)

// ---------------- scratch (device globals; no allocation) ----------------
__device__ float    g_s1[8], g_d1[8];
__device__ int      g_ei_is64, g_b_is64;
__device__ int      g_batch[N_NODES];
__device__ int      g_deg[N_NODES];
__device__ int      g_incl[N_NODES];
__device__ int      g_bsum[N_SBLK];
__device__ int      g_boff[N_SBLK];
__device__ int      g_rowstart[N_NODES + 1];
__device__ int      g_cursor[N_NODES];
__device__ int      g_csr_src[E_TOT];
__device__ float    g_t1  [N_NODES * 8];
__device__ float    g_h2  [N_NODES * 128];
__device__ float    g_as2 [N_NODES * 8];
__device__ float    g_ad2 [N_NODES * 8];
__device__ float    g_sums[N_GRAPHS * 16];

__device__ __forceinline__ float lrelu(float v) {
    return v > 0.f ? v : NEG_SLOPE * v;
}

// packed f32x2 helpers
__device__ __forceinline__ unsigned long long pack2(float lo, float hi) {
    unsigned long long r;
    asm("mov.b64 %0, {%1, %2};" : "=l"(r) : "f"(lo), "f"(hi));
    return r;
}
__device__ __forceinline__ void unpack2(unsigned long long p, float& lo, float& hi) {
    asm("mov.b64 {%0, %1}, %2;" : "=f"(lo), "=f"(hi) : "l"(p));
}
__device__ __forceinline__ void ffma2(unsigned long long& acc,
                                      unsigned long long a,
                                      unsigned long long b) {
    asm("fma.rn.f32x2 %0, %1, %2, %0;" : "+l"(acc) : "l"(a), "l"(b));
}

// ---------------- setup ----------------

// detect dtypes + prep s1/d1 + zero sums + rowstart[N]
__global__ void k_misc(const int* __restrict__ ei,
                       const int* __restrict__ ba,
                       const float* __restrict__ W1,
                       const float* __restrict__ att_src1,
                       const float* __restrict__ att_dst1) {
    __shared__ int s_e, s_b;
    int t = threadIdx.x;  // 64 threads
    if (t == 0) { s_e = 1; s_b = 1; }
    __syncthreads();
    int we = 2 * (t * 24999 + 13) + 1;          // < 3,200,000
    if (ei[we] != 0) atomicExch(&s_e, 0);
    int wb = (N_NODES - 1) - 2 * t;             // odd indices, in-bounds
    if (ba[wb] != 0) atomicExch(&s_b, 0);
    __syncthreads();
    if (t == 0) {
        g_ei_is64 = s_e;
        g_b_is64  = s_b;
        g_rowstart[N_NODES] = E_TOT;
    }
    if (t < 8) {
        float a = 0.f, b = 0.f;
        for (int c = 0; c < 8; c++) {
            a += W1[t * 8 + c] * att_src1[t * 8 + c];
            b += W1[t * 8 + c] * att_dst1[t * 8 + c];
        }
        g_s1[t] = a;
        g_d1[t] = b;
    }
    for (int i = t; i < N_GRAPHS * 16; i += 64) g_sums[i] = 0.f;
}

__global__ void k_zero() {
    int i = blockIdx.x * blockDim.x + threadIdx.x;
    if (i < N_NODES) g_deg[i] = 0;
}

// degree histogram straight from edge_index + batch conversion (fused)
__global__ void k_hist(const void* __restrict__ eiv,
                       const void* __restrict__ bav) {
    int i = blockIdx.x * blockDim.x + threadIdx.x;
    if (i < E_TOT) {
        int d;
        if (i < N_EDGES) {
            d = g_ei_is64 ? (int)((const long long*)eiv)[N_EDGES + i]
                          : ((const int*)eiv)[N_EDGES + i];
        } else {
            d = i - N_EDGES;
        }
        atomicAdd(&g_deg[d], 1);
    }
    if (i < N_NODES) {
        g_batch[i] = g_b_is64 ? (int)((const long long*)bav)[i]
                              : ((const int*)bav)[i];
    }
}

// ---- two-level scan ----
__global__ void k_scan1() {
    __shared__ int sh[SCAN_BLK];
    int t = threadIdx.x;
    int i = blockIdx.x * SCAN_BLK + t;
    int v = (i < N_NODES) ? g_deg[i] : 0;
    sh[t] = v;
    __syncthreads();
#pragma unroll
    for (int off = 1; off < SCAN_BLK; off <<= 1) {
        int tmp = (t >= off) ? sh[t - off] : 0;
        __syncthreads();
        sh[t] += tmp;
        __syncthreads();
    }
    if (i < N_NODES) g_incl[i] = sh[t];
    if (t == SCAN_BLK - 1) g_bsum[blockIdx.x] = sh[t];
}

__global__ void k_scan2() {
    __shared__ int sh[128];
    int t = threadIdx.x;
    int v = (t < N_SBLK) ? g_bsum[t] : 0;
    sh[t] = v;
    __syncthreads();
#pragma unroll
    for (int off = 1; off < 128; off <<= 1) {
        int tmp = (t >= off) ? sh[t - off] : 0;
        __syncthreads();
        sh[t] += tmp;
        __syncthreads();
    }
    if (t < N_SBLK) g_boff[t] = sh[t] - v;
}

__global__ void k_scan3() {
    int i = blockIdx.x * blockDim.x + threadIdx.x;
    if (i >= N_NODES) return;
    int rs = g_incl[i] - g_deg[i] + g_boff[i >> 10];
    g_rowstart[i] = rs;
    g_cursor[i]   = rs;
}

// scatter straight from edge_index
__global__ void k_scatter(const void* __restrict__ eiv) {
    int i = blockIdx.x * blockDim.x + threadIdx.x;
    if (i >= E_TOT) return;
    int s, d;
    if (i < N_EDGES) {
        if (g_ei_is64) {
            const long long* ei = (const long long*)eiv;
            s = (int)ei[i];
            d = (int)ei[N_EDGES + i];
        } else {
            const int* ei = (const int*)eiv;
            s = ei[i];
            d = ei[N_EDGES + i];
        }
    } else {
        s = i - N_EDGES;
        d = s;
    }
    int p = atomicAdd(&g_cursor[d], 1);
    g_csr_src[p] = s;
}

// ---- layer 1: warp per dst node, smem-staged xs ----
__global__ void __launch_bounds__(256) k_l1(const float* __restrict__ x) {
    __shared__ float s_x[8][CAP1];
    int w = (blockIdx.x * blockDim.x + threadIdx.x) >> 5;
    if (w >= N_NODES) return;
    int wl = (threadIdx.x >> 5);
    int lane = threadIdx.x & 31;
    int eo = lane >> 3, h = lane & 7;
    int start = g_rowstart[w], end = g_rowstart[w + 1];
    int deg = end - start;
    float cs = g_s1[h];
    float cd = g_d1[h] * x[w];

    if (deg <= CAP1) {
        for (int j = lane; j < deg; j += 32)
            s_x[wl][j] = x[g_csr_src[start + j]];
        __syncwarp();
        float m = NEG_BIG;
        for (int i = eo; i < deg; i += 4)
            m = fmaxf(m, lrelu(fmaf(s_x[wl][i], cs, cd)));
#pragma unroll
        for (int off = 8; off <= 16; off <<= 1)
            m = fmaxf(m, __shfl_xor_sync(0xffffffffu, m, off));
        float den = 0.f, num = 0.f;
        for (int i = eo; i < deg; i += 4) {
            float xs = s_x[wl][i];
            float wj = __expf(lrelu(fmaf(xs, cs, cd)) - m);
            den += wj;
            num += wj * xs;
        }
#pragma unroll
        for (int off = 8; off <= 16; off <<= 1) {
            den += __shfl_xor_sync(0xffffffffu, den, off);
            num += __shfl_xor_sync(0xffffffffu, num, off);
        }
        if (lane < 8) g_t1[w * 8 + h] = num / den;
    } else {
        float m = NEG_BIG, den = 0.f, num = 0.f;
        for (int j = start + eo; j < end; j += 4) {
            float xs = x[g_csr_src[j]];
            float e = lrelu(fmaf(xs, cs, cd));
            float nm = fmaxf(m, e);
            float r = __expf(m - nm);
            float wj = __expf(e - nm);
            den = den * r + wj;
            num = num * r + wj * xs;
            m = nm;
        }
#pragma unroll
        for (int off = 8; off <= 16; off <<= 1) {
            float m2 = __shfl_xor_sync(0xffffffffu, m,   off);
            float d2 = __shfl_xor_sync(0xffffffffu, den, off);
            float n2 = __shfl_xor_sync(0xffffffffu, num, off);
            float nm = fmaxf(m, m2);
            float r1 = __expf(m - nm), r2 = __expf(m2 - nm);
            den = den * r1 + d2 * r2;
            num = num * r1 + n2 * r2;
            m = nm;
        }
        if (lane < 8) g_t1[w * 8 + h] = num / den;
    }
}

// ---- GEMM2 + fused elu input + fused att2 epilogue ----
__global__ void __launch_bounds__(128) k_gemm2(const float* __restrict__ W1,
                                               const float* __restrict__ b1,
                                               const float* __restrict__ W2,
                                               const float* __restrict__ att_src2,
                                               const float* __restrict__ att_dst2) {
    __shared__ float s_in[16][64];
    int t = threadIdx.x;
    int n0 = blockIdx.x * 16;
    for (int e = t; e < 1024; e += 128) {
        int nn = e >> 6, j = e & 63;
        float v = fmaf(g_t1[(n0 + nn) * 8 + (j >> 3)], W1[j], b1[j]);
        s_in[nn][j] = v > 0.f ? v : (__expf(v) - 1.f);
    }
    __syncthreads();
    int lane = t & 31;
    int ng = t >> 5;
    int c = lane * 4;
    int h = lane >> 2;
    unsigned long long acc01[4], acc23[4];
#pragma unroll
    for (int i = 0; i < 4; i++) { acc01[i] = 0ull; acc23[i] = 0ull; }
    const float* w2p = &W2[c];
#pragma unroll 4
    for (int k = 0; k < 64; k++) {
        float4 wv = *reinterpret_cast<const float4*>(w2p + k * 128);
        unsigned long long s01 = pack2(s_in[ng * 4 + 0][k], s_in[ng * 4 + 1][k]);
        unsigned long long s23 = pack2(s_in[ng * 4 + 2][k], s_in[ng * 4 + 3][k]);
        unsigned long long w0 = pack2(wv.x, wv.x);
        unsigned long long w1 = pack2(wv.y, wv.y);
        unsigned long long w2 = pack2(wv.z, wv.z);
        unsigned long long w3 = pack2(wv.w, wv.w);
        ffma2(acc01[0], w0, s01); ffma2(acc23[0], w0, s23);
        ffma2(acc01[1], w1, s01); ffma2(acc23[1], w1, s23);
        ffma2(acc01[2], w2, s01); ffma2(acc23[2], w2, s23);
        ffma2(acc01[3], w3, s01); ffma2(acc23[3], w3, s23);
    }
    float4 av = *reinterpret_cast<const float4*>(&att_src2[c]);
    float4 dv = *reinterpret_cast<const float4*>(&att_dst2[c]);
    float4 row[4];
    {
        float lo[4], hi[4];
#pragma unroll
        for (int i = 0; i < 4; i++) unpack2(acc01[i], lo[i], hi[i]);
        row[0] = make_float4(lo[0], lo[1], lo[2], lo[3]);
        row[1] = make_float4(hi[0], hi[1], hi[2], hi[3]);
#pragma unroll
        for (int i = 0; i < 4; i++) unpack2(acc23[i], lo[i], hi[i]);
        row[2] = make_float4(lo[0], lo[1], lo[2], lo[3]);
        row[3] = make_float4(hi[0], hi[1], hi[2], hi[3]);
    }
    int nb = n0 + ng * 4;
#pragma unroll
    for (int r = 0; r < 4; r++) {
        *reinterpret_cast<float4*>(&g_h2[(nb + r) * 128 + c]) = row[r];
        float pa = row[r].x * av.x + row[r].y * av.y + row[r].z * av.z + row[r].w * av.w;
        float pd = row[r].x * dv.x + row[r].y * dv.y + row[r].z * dv.z + row[r].w * dv.w;
        pa += __shfl_xor_sync(0xffffffffu, pa, 1);
        pd += __shfl_xor_sync(0xffffffffu, pd, 1);
        pa += __shfl_xor_sync(0xffffffffu, pa, 2);
        pd += __shfl_xor_sync(0xffffffffu, pd, 2);
        if ((lane & 3) == 0) {
            g_as2[(nb + r) * 8 + h] = pa;
            g_ad2[(nb + r) * 8 + h] = pd;
        }
    }
}

// ---- layer 2 fused: smem-staged weights + src, 4x-unrolled gather, pool ----
__global__ void __launch_bounds__(256) k_l2() {
    __shared__ float s_w[8][8 * SWS];  // [warp][h*SWS + slot]
    __shared__ int   s_s[8][CAP2];     // [warp][slot]
    int d = (blockIdx.x * blockDim.x + threadIdx.x) >> 5;
    if (d >= N_NODES) return;
    int wl = threadIdx.x >> 5;
    int lane = threadIdx.x & 31;
    int start = g_rowstart[d];
    int deg = g_rowstart[d + 1] - start;
    int h = lane & 7, eo = lane >> 3;
    float ad = g_ad2[d * 8 + h];

    float ax = 0.f, ay = 0.f, az = 0.f, aw = 0.f;
    int hh = lane >> 2;
    float dh;

    if (deg <= CAP2) {
        // stage src ids
        for (int j = lane; j < deg; j += 32)
            s_s[wl][j] = g_csr_src[start + j];
        __syncwarp();
        // pass 0: logits + max (no exp)
        float m = NEG_BIG;
        for (int i = eo; i < deg; i += 4) {
            int s = s_s[wl][i];
            float e = lrelu(g_as2[s * 8 + h] + ad);
            s_w[wl][h * SWS + i] = e;
            m = fmaxf(m, e);
        }
#pragma unroll
        for (int off = 8; off <= 16; off <<= 1)
            m = fmaxf(m, __shfl_xor_sync(0xffffffffu, m, off));
        __syncwarp();
        // pass 1: weights in place + den (8 exp/edge total)
        float den = 0.f;
        for (int i = eo; i < deg; i += 4) {
            float wgt = __expf(s_w[wl][h * SWS + i] - m);
            s_w[wl][h * SWS + i] = wgt;
            den += wgt;
        }
#pragma unroll
        for (int off = 8; off <= 16; off <<= 1)
            den += __shfl_xor_sync(0xffffffffu, den, off);
        dh = __shfl_sync(0xffffffffu, den, hh);
        __syncwarp();
        // pass B: 4x-unrolled weighted gather of h2 rows
        const float* wrow = &s_w[wl][hh * SWS];
        int k = 0;
        for (; k + 3 < deg; k += 4) {
            int s0 = s_s[wl][k], s1 = s_s[wl][k + 1];
            int s2 = s_s[wl][k + 2], s3 = s_s[wl][k + 3];
            float w0 = wrow[k], w1 = wrow[k + 1];
            float w2 = wrow[k + 2], w3 = wrow[k + 3];
            float4 v0 = *reinterpret_cast<const float4*>(&g_h2[s0 * 128 + lane * 4]);
            float4 v1 = *reinterpret_cast<const float4*>(&g_h2[s1 * 128 + lane * 4]);
            float4 v2 = *reinterpret_cast<const float4*>(&g_h2[s2 * 128 + lane * 4]);
            float4 v3 = *reinterpret_cast<const float4*>(&g_h2[s3 * 128 + lane * 4]);
            ax += w0 * v0.x + w1 * v1.x + w2 * v2.x + w3 * v3.x;
            ay += w0 * v0.y + w1 * v1.y + w2 * v2.y + w3 * v3.y;
            az += w0 * v0.z + w1 * v1.z + w2 * v2.z + w3 * v3.z;
            aw += w0 * v0.w + w1 * v1.w + w2 * v2.w + w3 * v3.w;
        }
        for (; k < deg; k++) {
            int s0 = s_s[wl][k];
            float w0 = wrow[k];
            float4 v0 = *reinterpret_cast<const float4*>(&g_h2[s0 * 128 + lane * 4]);
            ax += w0 * v0.x; ay += w0 * v0.y; az += w0 * v0.z; aw += w0 * v0.w;
        }
    } else {
        // fallback: recompute path (statistically never)
        float m = NEG_BIG, den = 0.f;
        for (int j = start + eo; j < start + deg; j += 4) {
            int s = g_csr_src[j];
            float e = lrelu(g_as2[s * 8 + h] + ad);
            float nm = fmaxf(m, e);
            den = den * __expf(m - nm) + __expf(e - nm);
            m = nm;
        }
#pragma unroll
        for (int off = 8; off <= 16; off <<= 1) {
            float m2 = __shfl_xor_sync(0xffffffffu, m,   off);
            float d2 = __shfl_xor_sync(0xffffffffu, den, off);
            float nm = fmaxf(m, m2);
            den = den * __expf(m - nm) + d2 * __expf(m2 - nm);
            m = nm;
        }
        float mh  = __shfl_sync(0xffffffffu, m,   hh);
        dh        = __shfl_sync(0xffffffffu, den, hh);
        float adh = __shfl_sync(0xffffffffu, ad,  hh);
        for (int j = start; j < start + deg; j++) {
            int s0 = g_csr_src[j];
            float w0 = __expf(lrelu(g_as2[s0 * 8 + hh] + adh) - mh);
            float4 v0 = *reinterpret_cast<const float4*>(&g_h2[s0 * 128 + lane * 4]);
            ax += w0 * v0.x; ay += w0 * v0.y; az += w0 * v0.z; aw += w0 * v0.w;
        }
    }

    float inv = 0.125f / dh;
    ax *= inv; ay *= inv; az *= inv; aw *= inv;
#pragma unroll
    for (int off = 4; off <= 16; off <<= 1) {
        ax += __shfl_xor_sync(0xffffffffu, ax, off);
        ay += __shfl_xor_sync(0xffffffffu, ay, off);
        az += __shfl_xor_sync(0xffffffffu, az, off);
        aw += __shfl_xor_sync(0xffffffffu, aw, off);
    }
    int g = g_batch[d];
    if (lane < 4) {
        float* dst = &g_sums[g * 16 + lane * 4];
        atomicAdd(dst + 0, ax);
        atomicAdd(dst + 1, ay);
        atomicAdd(dst + 2, az);
        atomicAdd(dst + 3, aw);
    }
}

// counts via binary search on sorted batch; pooled = sums/cnt + b2; FC
__global__ void k_final(const float* __restrict__ b2,
                        const float* __restrict__ Wfc,
                        const float* __restrict__ bfc,
                        float* __restrict__ out) {
    __shared__ int s_lb[N_GRAPHS + 1];
    int g = threadIdx.x;
    if (g < N_GRAPHS) {
        int lo = 0, hi = N_NODES;
        while (lo < hi) {
            int mid = (lo + hi) >> 1;
            if (g_batch[mid] < g) lo = mid + 1; else hi = mid;
        }
        s_lb[g] = lo;
        if (g == 0) s_lb[N_GRAPHS] = N_NODES;
    }
    __syncthreads();
    if (g >= N_GRAPHS) return;
    float cnt = (float)(s_lb[g + 1] - s_lb[g]);
    float inv = 1.f / fmaxf(cnt, 1.f);
    float acc[4] = {bfc[0], bfc[1], bfc[2], bfc[3]};
#pragma unroll
    for (int c = 0; c < 16; c++) {
        float p = g_sums[g * 16 + c] * inv + b2[c];
#pragma unroll
        for (int o = 0; o < 4; o++) acc[o] += p * Wfc[c * 4 + o];
    }
#pragma unroll
    for (int o = 0; o < 4; o++) out[g * 4 + o] = acc[o];
}

// ---------------- launch ----------------
extern "C" void kernel_launch(void* const* d_in, const int* in_sizes, int n_in,
                              void* d_out, int out_size) {
    const float* x        = (const float*)d_in[0];
    const float* W1       = (const float*)d_in[1];
    const float* att_src1 = (const float*)d_in[2];
    const float* att_dst1 = (const float*)d_in[3];
    const float* b1       = (const float*)d_in[4];
    const float* W2       = (const float*)d_in[5];
    const float* att_src2 = (const float*)d_in[6];
    const float* att_dst2 = (const float*)d_in[7];
    const float* b2       = (const float*)d_in[8];
    const float* Wfc      = (const float*)d_in[9];
    const float* bfc      = (const float*)d_in[10];
    const void*  ei       = d_in[11];
    const void*  batch    = d_in[12];
    float* out = (float*)d_out;

    const int T = 256;
    k_misc<<<1, 64>>>((const int*)ei, (const int*)batch, W1, att_src1, att_dst1);
    k_zero<<<(N_NODES + T - 1) / T, T>>>();
    k_hist<<<(E_TOT + T - 1) / T, T>>>(ei, batch);
    k_scan1<<<N_SBLK, SCAN_BLK>>>();
    k_scan2<<<1, 128>>>();
    k_scan3<<<(N_NODES + T - 1) / T, T>>>();
    k_scatter<<<(E_TOT + T - 1) / T, T>>>(ei);

    k_l1<<<(N_NODES * 32 + T - 1) / T, T>>>(x);
    k_gemm2<<<N_NODES / 16, 128>>>(W1, b1, W2, att_src2, att_dst2);
    k_l2<<<(N_NODES * 32 + T - 1) / T, T>>>();
    k_final<<<1, 64>>>(b2, Wfc, bfc, out);
}

// round 7
// speedup vs baseline: 1.1936x; 1.1936x over previous
#include <cuda_runtime.h>
#include <cuda_bf16.h>

#define N_NODES 100000
#define N_EDGES 1600000
#define E_TOT   (N_EDGES + N_NODES)
#define N_GRAPHS 64
#define NEG_SLOPE 0.2f
#define NEG_BIG  -1e30f
#define SCAN_BLK 1024
#define N_SBLK   ((N_NODES + SCAN_BLK - 1) / SCAN_BLK)   // 98
#define CAP1     100     // layer-1 per-warp slot capacity
#define CAP2     64      // layer-2 per-warp slot capacity
#define SWS      68      // padded head stride for s_w (bank-conflict-free)

// ---------------- scratch (device globals; no allocation) ----------------
__device__ float    g_s1[8], g_d1[8];
__device__ int      g_ei_is64, g_b_is64;
__device__ int      g_batch[N_NODES];
__device__ int      g_deg[N_NODES];
__device__ int      g_incl[N_NODES];
__device__ int      g_bsum[N_SBLK];
__device__ int      g_boff[N_SBLK];
__device__ int      g_rowstart[N_NODES + 1];
__device__ int      g_cursor[N_NODES];
__device__ int      g_csr_src[E_TOT];
__device__ float    g_t1  [N_NODES * 8];
__device__ __nv_bfloat162 g_h2b[N_NODES * 64];   // h2 in bf16 (message values)
__device__ float    g_as2 [N_NODES * 8];
__device__ float    g_ad2 [N_NODES * 8];
__device__ float    g_sums[N_GRAPHS * 16];

__device__ __forceinline__ float lrelu(float v) {
    return v > 0.f ? v : NEG_SLOPE * v;
}

// packed f32x2 helpers
__device__ __forceinline__ unsigned long long pack2(float lo, float hi) {
    unsigned long long r;
    asm("mov.b64 %0, {%1, %2};" : "=l"(r) : "f"(lo), "f"(hi));
    return r;
}
__device__ __forceinline__ void unpack2(unsigned long long p, float& lo, float& hi) {
    asm("mov.b64 {%0, %1}, %2;" : "=f"(lo), "=f"(hi) : "l"(p));
}
__device__ __forceinline__ void ffma2(unsigned long long& acc,
                                      unsigned long long a,
                                      unsigned long long b) {
    asm("fma.rn.f32x2 %0, %1, %2, %0;" : "+l"(acc) : "l"(a), "l"(b));
}

// ---------------- setup ----------------

__global__ void k_misc(const int* __restrict__ ei,
                       const int* __restrict__ ba,
                       const float* __restrict__ W1,
                       const float* __restrict__ att_src1,
                       const float* __restrict__ att_dst1) {
    __shared__ int s_e, s_b;
    int t = threadIdx.x;  // 64 threads
    if (t == 0) { s_e = 1; s_b = 1; }
    __syncthreads();
    int we = 2 * (t * 24999 + 13) + 1;          // < 3,200,000
    if (ei[we] != 0) atomicExch(&s_e, 0);
    int wb = (N_NODES - 1) - 2 * t;             // odd indices, in-bounds
    if (ba[wb] != 0) atomicExch(&s_b, 0);
    __syncthreads();
    if (t == 0) {
        g_ei_is64 = s_e;
        g_b_is64  = s_b;
        g_rowstart[N_NODES] = E_TOT;
    }
    if (t < 8) {
        float a = 0.f, b = 0.f;
        for (int c = 0; c < 8; c++) {
            a += W1[t * 8 + c] * att_src1[t * 8 + c];
            b += W1[t * 8 + c] * att_dst1[t * 8 + c];
        }
        g_s1[t] = a;
        g_d1[t] = b;
    }
    for (int i = t; i < N_GRAPHS * 16; i += 64) g_sums[i] = 0.f;
}

__global__ void k_zero() {
    int i = blockIdx.x * blockDim.x + threadIdx.x;
    if (i < N_NODES) g_deg[i] = 0;
}

__global__ void k_hist(const void* __restrict__ eiv,
                       const void* __restrict__ bav) {
    int i = blockIdx.x * blockDim.x + threadIdx.x;
    if (i < E_TOT) {
        int d;
        if (i < N_EDGES) {
            d = g_ei_is64 ? (int)((const long long*)eiv)[N_EDGES + i]
                          : ((const int*)eiv)[N_EDGES + i];
        } else {
            d = i - N_EDGES;
        }
        atomicAdd(&g_deg[d], 1);
    }
    if (i < N_NODES) {
        g_batch[i] = g_b_is64 ? (int)((const long long*)bav)[i]
                              : ((const int*)bav)[i];
    }
}

// ---- two-level scan ----
__global__ void k_scan1() {
    __shared__ int sh[SCAN_BLK];
    int t = threadIdx.x;
    int i = blockIdx.x * SCAN_BLK + t;
    int v = (i < N_NODES) ? g_deg[i] : 0;
    sh[t] = v;
    __syncthreads();
#pragma unroll
    for (int off = 1; off < SCAN_BLK; off <<= 1) {
        int tmp = (t >= off) ? sh[t - off] : 0;
        __syncthreads();
        sh[t] += tmp;
        __syncthreads();
    }
    if (i < N_NODES) g_incl[i] = sh[t];
    if (t == SCAN_BLK - 1) g_bsum[blockIdx.x] = sh[t];
}

__global__ void k_scan2() {
    __shared__ int sh[128];
    int t = threadIdx.x;
    int v = (t < N_SBLK) ? g_bsum[t] : 0;
    sh[t] = v;
    __syncthreads();
#pragma unroll
    for (int off = 1; off < 128; off <<= 1) {
        int tmp = (t >= off) ? sh[t - off] : 0;
        __syncthreads();
        sh[t] += tmp;
        __syncthreads();
    }
    if (t < N_SBLK) g_boff[t] = sh[t] - v;
}

__global__ void k_scan3() {
    int i = blockIdx.x * blockDim.x + threadIdx.x;
    if (i >= N_NODES) return;
    int rs = g_incl[i] - g_deg[i] + g_boff[i >> 10];
    g_rowstart[i] = rs;
    g_cursor[i]   = rs;
}

__global__ void k_scatter(const void* __restrict__ eiv) {
    int i = blockIdx.x * blockDim.x + threadIdx.x;
    if (i >= E_TOT) return;
    int s, d;
    if (i < N_EDGES) {
        if (g_ei_is64) {
            const long long* ei = (const long long*)eiv;
            s = (int)ei[i];
            d = (int)ei[N_EDGES + i];
        } else {
            const int* ei = (const int*)eiv;
            s = ei[i];
            d = ei[N_EDGES + i];
        }
    } else {
        s = i - N_EDGES;
        d = s;
    }
    int p = atomicAdd(&g_cursor[d], 1);
    g_csr_src[p] = s;
}

// ---- layer 1: warp per dst node, smem-staged xs ----
__global__ void __launch_bounds__(256) k_l1(const float* __restrict__ x) {
    __shared__ float s_x[8][CAP1];
    int w = (blockIdx.x * blockDim.x + threadIdx.x) >> 5;
    if (w >= N_NODES) return;
    int wl = (threadIdx.x >> 5);
    int lane = threadIdx.x & 31;
    int eo = lane >> 3, h = lane & 7;
    int start = g_rowstart[w], end = g_rowstart[w + 1];
    int deg = end - start;
    float cs = g_s1[h];
    float cd = g_d1[h] * x[w];

    if (deg <= CAP1) {
        for (int j = lane; j < deg; j += 32)
            s_x[wl][j] = x[g_csr_src[start + j]];
        __syncwarp();
        float m = NEG_BIG;
        for (int i = eo; i < deg; i += 4)
            m = fmaxf(m, lrelu(fmaf(s_x[wl][i], cs, cd)));
#pragma unroll
        for (int off = 8; off <= 16; off <<= 1)
            m = fmaxf(m, __shfl_xor_sync(0xffffffffu, m, off));
        float den = 0.f, num = 0.f;
        for (int i = eo; i < deg; i += 4) {
            float xs = s_x[wl][i];
            float wj = __expf(lrelu(fmaf(xs, cs, cd)) - m);
            den += wj;
            num += wj * xs;
        }
#pragma unroll
        for (int off = 8; off <= 16; off <<= 1) {
            den += __shfl_xor_sync(0xffffffffu, den, off);
            num += __shfl_xor_sync(0xffffffffu, num, off);
        }
        if (lane < 8) g_t1[w * 8 + h] = num / den;
    } else {
        float m = NEG_BIG, den = 0.f, num = 0.f;
        for (int j = start + eo; j < end; j += 4) {
            float xs = x[g_csr_src[j]];
            float e = lrelu(fmaf(xs, cs, cd));
            float nm = fmaxf(m, e);
            float r = __expf(m - nm);
            float wj = __expf(e - nm);
            den = den * r + wj;
            num = num * r + wj * xs;
            m = nm;
        }
#pragma unroll
        for (int off = 8; off <= 16; off <<= 1) {
            float m2 = __shfl_xor_sync(0xffffffffu, m,   off);
            float d2 = __shfl_xor_sync(0xffffffffu, den, off);
            float n2 = __shfl_xor_sync(0xffffffffu, num, off);
            float nm = fmaxf(m, m2);
            float r1 = __expf(m - nm), r2 = __expf(m2 - nm);
            den = den * r1 + d2 * r2;
            num = num * r1 + n2 * r2;
            m = nm;
        }
        if (lane < 8) g_t1[w * 8 + h] = num / den;
    }
}

// ---- GEMM2 + fused elu input + fused att2 epilogue; h2 stored bf16 ----
__global__ void __launch_bounds__(128) k_gemm2(const float* __restrict__ W1,
                                               const float* __restrict__ b1,
                                               const float* __restrict__ W2,
                                               const float* __restrict__ att_src2,
                                               const float* __restrict__ att_dst2) {
    __shared__ float s_in[16][64];
    int t = threadIdx.x;
    int n0 = blockIdx.x * 16;
    for (int e = t; e < 1024; e += 128) {
        int nn = e >> 6, j = e & 63;
        float v = fmaf(g_t1[(n0 + nn) * 8 + (j >> 3)], W1[j], b1[j]);
        s_in[nn][j] = v > 0.f ? v : (__expf(v) - 1.f);
    }
    __syncthreads();
    int lane = t & 31;
    int ng = t >> 5;
    int c = lane * 4;
    int h = lane >> 2;
    unsigned long long acc01[4], acc23[4];
#pragma unroll
    for (int i = 0; i < 4; i++) { acc01[i] = 0ull; acc23[i] = 0ull; }
    const float* w2p = &W2[c];
#pragma unroll 4
    for (int k = 0; k < 64; k++) {
        float4 wv = *reinterpret_cast<const float4*>(w2p + k * 128);
        unsigned long long s01 = pack2(s_in[ng * 4 + 0][k], s_in[ng * 4 + 1][k]);
        unsigned long long s23 = pack2(s_in[ng * 4 + 2][k], s_in[ng * 4 + 3][k]);
        unsigned long long w0 = pack2(wv.x, wv.x);
        unsigned long long w1 = pack2(wv.y, wv.y);
        unsigned long long w2 = pack2(wv.z, wv.z);
        unsigned long long w3 = pack2(wv.w, wv.w);
        ffma2(acc01[0], w0, s01); ffma2(acc23[0], w0, s23);
        ffma2(acc01[1], w1, s01); ffma2(acc23[1], w1, s23);
        ffma2(acc01[2], w2, s01); ffma2(acc23[2], w2, s23);
        ffma2(acc01[3], w3, s01); ffma2(acc23[3], w3, s23);
    }
    float4 av = *reinterpret_cast<const float4*>(&att_src2[c]);
    float4 dv = *reinterpret_cast<const float4*>(&att_dst2[c]);
    float4 row[4];
    {
        float lo[4], hi[4];
#pragma unroll
        for (int i = 0; i < 4; i++) unpack2(acc01[i], lo[i], hi[i]);
        row[0] = make_float4(lo[0], lo[1], lo[2], lo[3]);
        row[1] = make_float4(hi[0], hi[1], hi[2], hi[3]);
#pragma unroll
        for (int i = 0; i < 4; i++) unpack2(acc23[i], lo[i], hi[i]);
        row[2] = make_float4(lo[0], lo[1], lo[2], lo[3]);
        row[3] = make_float4(hi[0], hi[1], hi[2], hi[3]);
    }
    int nb = n0 + ng * 4;
#pragma unroll
    for (int r = 0; r < 4; r++) {
        // store bf16 message values (lane covers channels c..c+3 = 2 bf16x2 words)
        __nv_bfloat162 b0 = __float22bfloat162_rn(make_float2(row[r].x, row[r].y));
        __nv_bfloat162 b1v = __float22bfloat162_rn(make_float2(row[r].z, row[r].w));
        uint2 packed;
        packed.x = *reinterpret_cast<unsigned*>(&b0);
        packed.y = *reinterpret_cast<unsigned*>(&b1v);
        *reinterpret_cast<uint2*>(&g_h2b[(nb + r) * 64 + lane * 2]) = packed;
        // attention logits stay fp32
        float pa = row[r].x * av.x + row[r].y * av.y + row[r].z * av.z + row[r].w * av.w;
        float pd = row[r].x * dv.x + row[r].y * dv.y + row[r].z * dv.z + row[r].w * dv.w;
        pa += __shfl_xor_sync(0xffffffffu, pa, 1);
        pd += __shfl_xor_sync(0xffffffffu, pd, 1);
        pa += __shfl_xor_sync(0xffffffffu, pa, 2);
        pd += __shfl_xor_sync(0xffffffffu, pd, 2);
        if ((lane & 3) == 0) {
            g_as2[(nb + r) * 8 + h] = pa;
            g_ad2[(nb + r) * 8 + h] = pd;
        }
    }
}

__device__ __forceinline__ void acc_bf16(const uint2 v, float w,
                                         float& ax, float& ay, float& az, float& aw) {
    __nv_bfloat162 b0 = *reinterpret_cast<const __nv_bfloat162*>(&v.x);
    __nv_bfloat162 b1 = *reinterpret_cast<const __nv_bfloat162*>(&v.y);
    float2 f0 = __bfloat1622float2(b0);
    float2 f1 = __bfloat1622float2(b1);
    ax = fmaf(w, f0.x, ax);
    ay = fmaf(w, f0.y, ay);
    az = fmaf(w, f1.x, az);
    aw = fmaf(w, f1.y, aw);
}

// ---- layer 2 fused: smem-staged weights + src, bf16 gather, pool ----
__global__ void __launch_bounds__(256) k_l2() {
    __shared__ float s_w[8][8 * SWS];  // [warp][h*SWS + slot]
    __shared__ int   s_s[8][CAP2];     // [warp][slot]
    int d = (blockIdx.x * blockDim.x + threadIdx.x) >> 5;
    if (d >= N_NODES) return;
    int wl = threadIdx.x >> 5;
    int lane = threadIdx.x & 31;
    int start = g_rowstart[d];
    int deg = g_rowstart[d + 1] - start;
    int h = lane & 7, eo = lane >> 3;
    float ad = g_ad2[d * 8 + h];

    float ax = 0.f, ay = 0.f, az = 0.f, aw = 0.f;
    int hh = lane >> 2;
    float dh;

    if (deg <= CAP2) {
        for (int j = lane; j < deg; j += 32)
            s_s[wl][j] = g_csr_src[start + j];
        __syncwarp();
        float m = NEG_BIG;
        for (int i = eo; i < deg; i += 4) {
            int s = s_s[wl][i];
            float e = lrelu(g_as2[s * 8 + h] + ad);
            s_w[wl][h * SWS + i] = e;
            m = fmaxf(m, e);
        }
#pragma unroll
        for (int off = 8; off <= 16; off <<= 1)
            m = fmaxf(m, __shfl_xor_sync(0xffffffffu, m, off));
        __syncwarp();
        float den = 0.f;
        for (int i = eo; i < deg; i += 4) {
            float wgt = __expf(s_w[wl][h * SWS + i] - m);
            s_w[wl][h * SWS + i] = wgt;
            den += wgt;
        }
#pragma unroll
        for (int off = 8; off <= 16; off <<= 1)
            den += __shfl_xor_sync(0xffffffffu, den, off);
        dh = __shfl_sync(0xffffffffu, den, hh);
        __syncwarp();
        // pass B: 4x-unrolled weighted bf16 gather (lane = 4 channels of head hh)
        const float* wrow = &s_w[wl][hh * SWS];
        int k = 0;
        for (; k + 3 < deg; k += 4) {
            int s0 = s_s[wl][k], s1 = s_s[wl][k + 1];
            int s2 = s_s[wl][k + 2], s3 = s_s[wl][k + 3];
            float w0 = wrow[k], w1 = wrow[k + 1];
            float w2 = wrow[k + 2], w3 = wrow[k + 3];
            uint2 v0 = *reinterpret_cast<const uint2*>(&g_h2b[s0 * 64 + lane * 2]);
            uint2 v1 = *reinterpret_cast<const uint2*>(&g_h2b[s1 * 64 + lane * 2]);
            uint2 v2 = *reinterpret_cast<const uint2*>(&g_h2b[s2 * 64 + lane * 2]);
            uint2 v3 = *reinterpret_cast<const uint2*>(&g_h2b[s3 * 64 + lane * 2]);
            acc_bf16(v0, w0, ax, ay, az, aw);
            acc_bf16(v1, w1, ax, ay, az, aw);
            acc_bf16(v2, w2, ax, ay, az, aw);
            acc_bf16(v3, w3, ax, ay, az, aw);
        }
        for (; k < deg; k++) {
            int s0 = s_s[wl][k];
            float w0 = wrow[k];
            uint2 v0 = *reinterpret_cast<const uint2*>(&g_h2b[s0 * 64 + lane * 2]);
            acc_bf16(v0, w0, ax, ay, az, aw);
        }
    } else {
        // fallback (statistically never)
        float m = NEG_BIG, den = 0.f;
        for (int j = start + eo; j < start + deg; j += 4) {
            int s = g_csr_src[j];
            float e = lrelu(g_as2[s * 8 + h] + ad);
            float nm = fmaxf(m, e);
            den = den * __expf(m - nm) + __expf(e - nm);
            m = nm;
        }
#pragma unroll
        for (int off = 8; off <= 16; off <<= 1) {
            float m2 = __shfl_xor_sync(0xffffffffu, m,   off);
            float d2 = __shfl_xor_sync(0xffffffffu, den, off);
            float nm = fmaxf(m, m2);
            den = den * __expf(m - nm) + d2 * __expf(m2 - nm);
            m = nm;
        }
        float mh  = __shfl_sync(0xffffffffu, m,   hh);
        dh        = __shfl_sync(0xffffffffu, den, hh);
        float adh = __shfl_sync(0xffffffffu, ad,  hh);
        for (int j = start; j < start + deg; j++) {
            int s0 = g_csr_src[j];
            float w0 = __expf(lrelu(g_as2[s0 * 8 + hh] + adh) - mh);
            uint2 v0 = *reinterpret_cast<const uint2*>(&g_h2b[s0 * 64 + lane * 2]);
            acc_bf16(v0, w0, ax, ay, az, aw);
        }
    }

    float inv = 0.125f / dh;
    ax *= inv; ay *= inv; az *= inv; aw *= inv;
#pragma unroll
    for (int off = 4; off <= 16; off <<= 1) {
        ax += __shfl_xor_sync(0xffffffffu, ax, off);
        ay += __shfl_xor_sync(0xffffffffu, ay, off);
        az += __shfl_xor_sync(0xffffffffu, az, off);
        aw += __shfl_xor_sync(0xffffffffu, aw, off);
    }
    int g = g_batch[d];
    if (lane < 4) {
        float* dst = &g_sums[g * 16 + lane * 4];
        atomicAdd(dst + 0, ax);
        atomicAdd(dst + 1, ay);
        atomicAdd(dst + 2, az);
        atomicAdd(dst + 3, aw);
    }
}

// counts via binary search on sorted batch; pooled = sums/cnt + b2; FC
__global__ void k_final(const float* __restrict__ b2,
                        const float* __restrict__ Wfc,
                        const float* __restrict__ bfc,
                        float* __restrict__ out) {
    __shared__ int s_lb[N_GRAPHS + 1];
    int g = threadIdx.x;
    if (g < N_GRAPHS) {
        int lo = 0, hi = N_NODES;
        while (lo < hi) {
            int mid = (lo + hi) >> 1;
            if (g_batch[mid] < g) lo = mid + 1; else hi = mid;
        }
        s_lb[g] = lo;
        if (g == 0) s_lb[N_GRAPHS] = N_NODES;
    }
    __syncthreads();
    if (g >= N_GRAPHS) return;
    float cnt = (float)(s_lb[g + 1] - s_lb[g]);
    float inv = 1.f / fmaxf(cnt, 1.f);
    float acc[4] = {bfc[0], bfc[1], bfc[2], bfc[3]};
#pragma unroll
    for (int c = 0; c < 16; c++) {
        float p = g_sums[g * 16 + c] * inv + b2[c];
#pragma unroll
        for (int o = 0; o < 4; o++) acc[o] += p * Wfc[c * 4 + o];
    }
#pragma unroll
    for (int o = 0; o < 4; o++) out[g * 4 + o] = acc[o];
}

// ---------------- launch ----------------
extern "C" void kernel_launch(void* const* d_in, const int* in_sizes, int n_in,
                              void* d_out, int out_size) {
    const float* x        = (const float*)d_in[0];
    const float* W1       = (const float*)d_in[1];
    const float* att_src1 = (const float*)d_in[2];
    const float* att_dst1 = (const float*)d_in[3];
    const float* b1       = (const float*)d_in[4];
    const float* W2       = (const float*)d_in[5];
    const float* att_src2 = (const float*)d_in[6];
    const float* att_dst2 = (const float*)d_in[7];
    const float* b2       = (const float*)d_in[8];
    const float* Wfc      = (const float*)d_in[9];
    const float* bfc      = (const float*)d_in[10];
    const void*  ei       = d_in[11];
    const void*  batch    = d_in[12];
    float* out = (float*)d_out;

    const int T = 256;
    k_misc<<<1, 64>>>((const int*)ei, (const int*)batch, W1, att_src1, att_dst1);
    k_zero<<<(N_NODES + T - 1) / T, T>>>();
    k_hist<<<(E_TOT + T - 1) / T, T>>>(ei, batch);
    k_scan1<<<N_SBLK, SCAN_BLK>>>();
    k_scan2<<<1, 128>>>();
    k_scan3<<<(N_NODES + T - 1) / T, T>>>();
    k_scatter<<<(E_TOT + T - 1) / T, T>>>(ei);

    k_l1<<<(N_NODES * 32 + T - 1) / T, T>>>(x);
    k_gemm2<<<N_NODES / 16, 128>>>(W1, b1, W2, att_src2, att_dst2);
    k_l2<<<(N_NODES * 32 + T - 1) / T, T>>>();
    k_final<<<1, 64>>>(b2, Wfc, bfc, out);
}

// round 9
// speedup vs baseline: 1.2076x; 1.0117x over previous
#include <cuda_runtime.h>
#include <cuda_bf16.h>

#define N_NODES 100000
#define N_EDGES 1600000
#define E_TOT   (N_EDGES + N_NODES)
#define N_GRAPHS 64
#define NEG_SLOPE 0.2f
#define NEG_BIG  -1e30f
#define SCAN_BLK 1024
#define N_SBLK   ((N_NODES + SCAN_BLK - 1) / SCAN_BLK)   // 98
#define CAP1     100     // layer-1 per-warp slot capacity
#define CAP2     64      // layer-2 per-warp slot capacity
#define SWS      68      // padded head stride for s_w (bank-conflict-free)

// ---------------- scratch (device globals; no allocation) ----------------
__device__ float    g_s1[8], g_d1[8];
__device__ int      g_ei_is64, g_b_is64;
__device__ int      g_batch[N_NODES];
__device__ int      g_deg[N_NODES];
__device__ int      g_incl[N_NODES];
__device__ int      g_bsum[N_SBLK];
__device__ int      g_rowstart[N_NODES + 1];
__device__ int      g_cursor[N_NODES];
__device__ int      g_csr_src[E_TOT];
__device__ float    g_t1  [N_NODES * 8];
__device__ __nv_bfloat162 g_h2b[N_NODES * 64];   // h2 in bf16 (message values)
__device__ float    g_as2 [N_NODES * 8];
__device__ float    g_ad2 [N_NODES * 8];
__device__ float    g_sums[N_GRAPHS * 16];

__device__ __forceinline__ float lrelu(float v) {
    return v > 0.f ? v : NEG_SLOPE * v;
}

// packed f32x2 helpers
__device__ __forceinline__ unsigned long long pack2(float lo, float hi) {
    unsigned long long r;
    asm("mov.b64 %0, {%1, %2};" : "=l"(r) : "f"(lo), "f"(hi));
    return r;
}
__device__ __forceinline__ void unpack2(unsigned long long p, float& lo, float& hi) {
    asm("mov.b64 {%0, %1}, %2;" : "=f"(lo), "=f"(hi) : "l"(p));
}
__device__ __forceinline__ void ffma2(unsigned long long& acc,
                                      unsigned long long a,
                                      unsigned long long b) {
    asm("fma.rn.f32x2 %0, %1, %2, %0;" : "+l"(acc) : "l"(a), "l"(b));
}

__device__ __forceinline__ void acc_bf16(const uint2 v, float w,
                                         float& ax, float& ay, float& az, float& aw) {
    __nv_bfloat162 b0 = *reinterpret_cast<const __nv_bfloat162*>(&v.x);
    __nv_bfloat162 b1 = *reinterpret_cast<const __nv_bfloat162*>(&v.y);
    float2 f0 = __bfloat1622float2(b0);
    float2 f1 = __bfloat1622float2(b1);
    ax = fmaf(w, f0.x, ax);
    ay = fmaf(w, f0.y, ay);
    az = fmaf(w, f1.x, az);
    aw = fmaf(w, f1.y, aw);
}

// ---------------- setup ----------------

// multi-block: zero deg/sums; block 0 also detects dtypes + preps s1/d1
__global__ void k_misc(const int* __restrict__ ei,
                       const int* __restrict__ ba,
                       const float* __restrict__ W1,
                       const float* __restrict__ att_src1,
                       const float* __restrict__ att_dst1) {
    int i = blockIdx.x * blockDim.x + threadIdx.x;
    if (i < N_NODES) g_deg[i] = 0;
    if (i < N_GRAPHS * 16) g_sums[i] = 0.f;
    if (blockIdx.x == 0) {
        __shared__ int s_e, s_b;
        int t = threadIdx.x;
        if (t == 0) { s_e = 1; s_b = 1; }
        __syncthreads();
        if (t < 64) {
            int we = 2 * (t * 24999 + 13) + 1;      // < 3,200,000
            if (ei[we] != 0) atomicExch(&s_e, 0);
            int wb = (N_NODES - 1) - 2 * t;         // odd, in-bounds
            if (ba[wb] != 0) atomicExch(&s_b, 0);
        }
        __syncthreads();
        if (t == 0) {
            g_ei_is64 = s_e;
            g_b_is64  = s_b;
            g_rowstart[N_NODES] = E_TOT;
        }
        if (t < 8) {
            float a = 0.f, b = 0.f;
            for (int c = 0; c < 8; c++) {
                a += W1[t * 8 + c] * att_src1[t * 8 + c];
                b += W1[t * 8 + c] * att_dst1[t * 8 + c];
            }
            g_s1[t] = a;
            g_d1[t] = b;
        }
    }
}

__global__ void k_hist(const void* __restrict__ eiv,
                       const void* __restrict__ bav) {
    int i = blockIdx.x * blockDim.x + threadIdx.x;
    if (i < E_TOT) {
        int d;
        if (i < N_EDGES) {
            d = g_ei_is64 ? (int)((const long long*)eiv)[N_EDGES + i]
                          : ((const int*)eiv)[N_EDGES + i];
        } else {
            d = i - N_EDGES;
        }
        atomicAdd(&g_deg[d], 1);
    }
    if (i < N_NODES) {
        g_batch[i] = g_b_is64 ? (int)((const long long*)bav)[i]
                              : ((const int*)bav)[i];
    }
}

// stage 1: per-block inclusive scan + block sums
__global__ void k_scan1() {
    __shared__ int sh[SCAN_BLK];
    int t = threadIdx.x;
    int i = blockIdx.x * SCAN_BLK + t;
    int v = (i < N_NODES) ? g_deg[i] : 0;
    sh[t] = v;
    __syncthreads();
#pragma unroll
    for (int off = 1; off < SCAN_BLK; off <<= 1) {
        int tmp = (t >= off) ? sh[t - off] : 0;
        __syncthreads();
        sh[t] += tmp;
        __syncthreads();
    }
    if (i < N_NODES) g_incl[i] = sh[t];
    if (t == SCAN_BLK - 1) g_bsum[blockIdx.x] = sh[t];
}

// stage 2 (fused): each 256-thread block computes its scan1-block prefix itself
__global__ void k_scan3() {
    __shared__ int s_boff;
    if (threadIdx.x < 32) {
        int sb = blockIdx.x >> 2;    // scan1 block index (1024/256)
        int acc = 0;
        for (int j = threadIdx.x; j < sb; j += 32) acc += g_bsum[j];
#pragma unroll
        for (int off = 16; off >= 1; off >>= 1)
            acc += __shfl_xor_sync(0xffffffffu, acc, off);
        if (threadIdx.x == 0) s_boff = acc;
    }
    __syncthreads();
    int i = blockIdx.x * blockDim.x + threadIdx.x;
    if (i >= N_NODES) return;
    int rs = g_incl[i] - g_deg[i] + s_boff;
    g_rowstart[i] = rs;
    g_cursor[i]   = rs;
}

__global__ void k_scatter(const void* __restrict__ eiv) {
    int i = blockIdx.x * blockDim.x + threadIdx.x;
    if (i >= E_TOT) return;
    int s, d;
    if (i < N_EDGES) {
        if (g_ei_is64) {
            const long long* ei = (const long long*)eiv;
            s = (int)ei[i];
            d = (int)ei[N_EDGES + i];
        } else {
            const int* ei = (const int*)eiv;
            s = ei[i];
            d = ei[N_EDGES + i];
        }
    } else {
        s = i - N_EDGES;
        d = s;
    }
    int p = atomicAdd(&g_cursor[d], 1);
    g_csr_src[p] = s;
}

// ---- layer 1: warp per dst node, smem-staged xs, no-max softmax ----
// |logit| <= |x|max*(|s1|+|d1|) ~ 15, so raw __expf is fp32-safe.
__global__ void __launch_bounds__(256) k_l1(const float* __restrict__ x) {
    __shared__ float s_x[8][CAP1];
    int w = (blockIdx.x * blockDim.x + threadIdx.x) >> 5;
    if (w >= N_NODES) return;
    int wl = (threadIdx.x >> 5);
    int lane = threadIdx.x & 31;
    int eo = lane >> 3, h = lane & 7;
    int start = g_rowstart[w], end = g_rowstart[w + 1];
    int deg = end - start;
    float cs = g_s1[h];
    float cd = g_d1[h] * x[w];

    if (deg <= CAP1) {
        for (int j = lane; j < deg; j += 32)
            s_x[wl][j] = x[g_csr_src[start + j]];
        __syncwarp();
        float den = 0.f, num = 0.f;
        for (int i = eo; i < deg; i += 4) {
            float xs = s_x[wl][i];
            float wj = __expf(lrelu(fmaf(xs, cs, cd)));
            den += wj;
            num += wj * xs;
        }
#pragma unroll
        for (int off = 8; off <= 16; off <<= 1) {
            den += __shfl_xor_sync(0xffffffffu, den, off);
            num += __shfl_xor_sync(0xffffffffu, num, off);
        }
        if (lane < 8) g_t1[w * 8 + h] = num / den;
    } else {
        // fallback: online softmax with max tracking (statistically never)
        float m = NEG_BIG, den = 0.f, num = 0.f;
        for (int j = start + eo; j < end; j += 4) {
            float xs = x[g_csr_src[j]];
            float e = lrelu(fmaf(xs, cs, cd));
            float nm = fmaxf(m, e);
            float r = __expf(m - nm);
            float wj = __expf(e - nm);
            den = den * r + wj;
            num = num * r + wj * xs;
            m = nm;
        }
#pragma unroll
        for (int off = 8; off <= 16; off <<= 1) {
            float m2 = __shfl_xor_sync(0xffffffffu, m,   off);
            float d2 = __shfl_xor_sync(0xffffffffu, den, off);
            float n2 = __shfl_xor_sync(0xffffffffu, num, off);
            float nm = fmaxf(m, m2);
            float r1 = __expf(m - nm), r2 = __expf(m2 - nm);
            den = den * r1 + d2 * r2;
            num = num * r1 + n2 * r2;
            m = nm;
        }
        if (lane < 8) g_t1[w * 8 + h] = num / den;
    }
}

// ---- GEMM2 + fused elu input + fused att2 epilogue; h2 stored bf16 ----
__global__ void __launch_bounds__(128) k_gemm2(const float* __restrict__ W1,
                                               const float* __restrict__ b1,
                                               const float* __restrict__ W2,
                                               const float* __restrict__ att_src2,
                                               const float* __restrict__ att_dst2) {
    __shared__ float s_in[16][64];
    int t = threadIdx.x;
    int n0 = blockIdx.x * 16;
    for (int e = t; e < 1024; e += 128) {
        int nn = e >> 6, j = e & 63;
        float v = fmaf(g_t1[(n0 + nn) * 8 + (j >> 3)], W1[j], b1[j]);
        s_in[nn][j] = v > 0.f ? v : (__expf(v) - 1.f);
    }
    __syncthreads();
    int lane = t & 31;
    int ng = t >> 5;
    int c = lane * 4;
    int h = lane >> 2;
    unsigned long long acc01[4], acc23[4];
#pragma unroll
    for (int i = 0; i < 4; i++) { acc01[i] = 0ull; acc23[i] = 0ull; }
    const float* w2p = &W2[c];
#pragma unroll 4
    for (int k = 0; k < 64; k++) {
        float4 wv = *reinterpret_cast<const float4*>(w2p + k * 128);
        unsigned long long s01 = pack2(s_in[ng * 4 + 0][k], s_in[ng * 4 + 1][k]);
        unsigned long long s23 = pack2(s_in[ng * 4 + 2][k], s_in[ng * 4 + 3][k]);
        unsigned long long w0 = pack2(wv.x, wv.x);
        unsigned long long w1 = pack2(wv.y, wv.y);
        unsigned long long w2 = pack2(wv.z, wv.z);
        unsigned long long w3 = pack2(wv.w, wv.w);
        ffma2(acc01[0], w0, s01); ffma2(acc23[0], w0, s23);
        ffma2(acc01[1], w1, s01); ffma2(acc23[1], w1, s23);
        ffma2(acc01[2], w2, s01); ffma2(acc23[2], w2, s23);
        ffma2(acc01[3], w3, s01); ffma2(acc23[3], w3, s23);
    }
    float4 av = *reinterpret_cast<const float4*>(&att_src2[c]);
    float4 dv = *reinterpret_cast<const float4*>(&att_dst2[c]);
    float4 row[4];
    {
        float lo[4], hi[4];
#pragma unroll
        for (int i = 0; i < 4; i++) unpack2(acc01[i], lo[i], hi[i]);
        row[0] = make_float4(lo[0], lo[1], lo[2], lo[3]);
        row[1] = make_float4(hi[0], hi[1], hi[2], hi[3]);
#pragma unroll
        for (int i = 0; i < 4; i++) unpack2(acc23[i], lo[i], hi[i]);
        row[2] = make_float4(lo[0], lo[1], lo[2], lo[3]);
        row[3] = make_float4(hi[0], hi[1], hi[2], hi[3]);
    }
    int nb = n0 + ng * 4;
#pragma unroll
    for (int r = 0; r < 4; r++) {
        __nv_bfloat162 b0 = __float22bfloat162_rn(make_float2(row[r].x, row[r].y));
        __nv_bfloat162 b1v = __float22bfloat162_rn(make_float2(row[r].z, row[r].w));
        uint2 packed;
        packed.x = *reinterpret_cast<unsigned*>(&b0);
        packed.y = *reinterpret_cast<unsigned*>(&b1v);
        *reinterpret_cast<uint2*>(&g_h2b[(nb + r) * 64 + lane * 2]) = packed;
        float pa = row[r].x * av.x + row[r].y * av.y + row[r].z * av.z + row[r].w * av.w;
        float pd = row[r].x * dv.x + row[r].y * dv.y + row[r].z * dv.z + row[r].w * dv.w;
        pa += __shfl_xor_sync(0xffffffffu, pa, 1);
        pd += __shfl_xor_sync(0xffffffffu, pd, 1);
        pa += __shfl_xor_sync(0xffffffffu, pa, 2);
        pd += __shfl_xor_sync(0xffffffffu, pd, 2);
        if ((lane & 3) == 0) {
            g_as2[(nb + r) * 8 + h] = pa;
            g_ad2[(nb + r) * 8 + h] = pd;
        }
    }
}

// ---- layer 2 fused: smem-staged weights + src, bf16 gather, pool ----
__global__ void __launch_bounds__(256) k_l2() {
    __shared__ float s_w[8][8 * SWS];  // [warp][h*SWS + slot]
    __shared__ int   s_s[8][CAP2];     // [warp][slot]
    int d = (blockIdx.x * blockDim.x + threadIdx.x) >> 5;
    if (d >= N_NODES) return;
    int wl = threadIdx.x >> 5;
    int lane = threadIdx.x & 31;
    int start = g_rowstart[d];
    int deg = g_rowstart[d + 1] - start;
    int h = lane & 7, eo = lane >> 3;
    float ad = g_ad2[d * 8 + h];

    float ax = 0.f, ay = 0.f, az = 0.f, aw = 0.f;
    int hh = lane >> 2;
    float dh;

    if (deg <= CAP2) {
        for (int j = lane; j < deg; j += 32)
            s_s[wl][j] = g_csr_src[start + j];
        __syncwarp();
        float m = NEG_BIG;
        for (int i = eo; i < deg; i += 4) {
            int s = s_s[wl][i];
            float e = lrelu(g_as2[s * 8 + h] + ad);
            s_w[wl][h * SWS + i] = e;
            m = fmaxf(m, e);
        }
#pragma unroll
        for (int off = 8; off <= 16; off <<= 1)
            m = fmaxf(m, __shfl_xor_sync(0xffffffffu, m, off));
        __syncwarp();
        float den = 0.f;
        for (int i = eo; i < deg; i += 4) {
            float wgt = __expf(s_w[wl][h * SWS + i] - m);
            s_w[wl][h * SWS + i] = wgt;
            den += wgt;
        }
#pragma unroll
        for (int off = 8; off <= 16; off <<= 1)
            den += __shfl_xor_sync(0xffffffffu, den, off);
        dh = __shfl_sync(0xffffffffu, den, hh);
        __syncwarp();
        const float* wrow = &s_w[wl][hh * SWS];
        int k = 0;
        for (; k + 3 < deg; k += 4) {
            int s0 = s_s[wl][k], s1 = s_s[wl][k + 1];
            int s2 = s_s[wl][k + 2], s3 = s_s[wl][k + 3];
            float w0 = wrow[k], w1 = wrow[k + 1];
            float w2 = wrow[k + 2], w3 = wrow[k + 3];
            uint2 v0 = *reinterpret_cast<const uint2*>(&g_h2b[s0 * 64 + lane * 2]);
            uint2 v1 = *reinterpret_cast<const uint2*>(&g_h2b[s1 * 64 + lane * 2]);
            uint2 v2 = *reinterpret_cast<const uint2*>(&g_h2b[s2 * 64 + lane * 2]);
            uint2 v3 = *reinterpret_cast<const uint2*>(&g_h2b[s3 * 64 + lane * 2]);
            acc_bf16(v0, w0, ax, ay, az, aw);
            acc_bf16(v1, w1, ax, ay, az, aw);
            acc_bf16(v2, w2, ax, ay, az, aw);
            acc_bf16(v3, w3, ax, ay, az, aw);
        }
        for (; k < deg; k++) {
            int s0 = s_s[wl][k];
            float w0 = wrow[k];
            uint2 v0 = *reinterpret_cast<const uint2*>(&g_h2b[s0 * 64 + lane * 2]);
            acc_bf16(v0, w0, ax, ay, az, aw);
        }
    } else {
        // fallback (statistically never)
        float m = NEG_BIG, den = 0.f;
        for (int j = start + eo; j < start + deg; j += 4) {
            int s = g_csr_src[j];
            float e = lrelu(g_as2[s * 8 + h] + ad);
            float nm = fmaxf(m, e);
            den = den * __expf(m - nm) + __expf(e - nm);
            m = nm;
        }
#pragma unroll
        for (int off = 8; off <= 16; off <<= 1) {
            float m2 = __shfl_xor_sync(0xffffffffu, m,   off);
            float d2 = __shfl_xor_sync(0xffffffffu, den, off);
            float nm = fmaxf(m, m2);
            den = den * __expf(m - nm) + d2 * __expf(m2 - nm);
            m = nm;
        }
        float mh  = __shfl_sync(0xffffffffu, m,   hh);
        dh        = __shfl_sync(0xffffffffu, den, hh);
        float adh = __shfl_sync(0xffffffffu, ad,  hh);
        for (int j = start; j < start + deg; j++) {
            int s0 = g_csr_src[j];
            float w0 = __expf(lrelu(g_as2[s0 * 8 + hh] + adh) - mh);
            uint2 v0 = *reinterpret_cast<const uint2*>(&g_h2b[s0 * 64 + lane * 2]);
            acc_bf16(v0, w0, ax, ay, az, aw);
        }
    }

    float inv = 0.125f / dh;
    ax *= inv; ay *= inv; az *= inv; aw *= inv;
#pragma unroll
    for (int off = 4; off <= 16; off <<= 1) {
        ax += __shfl_xor_sync(0xffffffffu, ax, off);
        ay += __shfl_xor_sync(0xffffffffu, ay, off);
        az += __shfl_xor_sync(0xffffffffu, az, off);
        aw += __shfl_xor_sync(0xffffffffu, aw, off);
    }
    int g = g_batch[d];
    if (lane < 4) {
        float* dst = &g_sums[g * 16 + lane * 4];
        atomicAdd(dst + 0, ax);
        atomicAdd(dst + 1, ay);
        atomicAdd(dst + 2, az);
        atomicAdd(dst + 3, aw);
    }
}

// counts via binary search on sorted batch; pooled = sums/cnt + b2; FC
__global__ void k_final(const float* __restrict__ b2,
                        const float* __restrict__ Wfc,
                        const float* __restrict__ bfc,
                        float* __restrict__ out) {
    __shared__ int s_lb[N_GRAPHS + 1];
    int g = threadIdx.x;
    if (g < N_GRAPHS) {
        int lo = 0, hi = N_NODES;
        while (lo < hi) {
            int mid = (lo + hi) >> 1;
            if (g_batch[mid] < g) lo = mid + 1; else hi = mid;
        }
        s_lb[g] = lo;
        if (g == 0) s_lb[N_GRAPHS] = N_NODES;
    }
    __syncthreads();
    if (g >= N_GRAPHS) return;
    float cnt = (float)(s_lb[g + 1] - s_lb[g]);
    float inv = 1.f / fmaxf(cnt, 1.f);
    float acc[4] = {bfc[0], bfc[1], bfc[2], bfc[3]};
#pragma unroll
    for (int c = 0; c < 16; c++) {
        float p = g_sums[g * 16 + c] * inv + b2[c];
#pragma unroll
        for (int o = 0; o < 4; o++) acc[o] += p * Wfc[c * 4 + o];
    }
#pragma unroll
    for (int o = 0; o < 4; o++) out[g * 4 + o] = acc[o];
}

// ---------------- launch ----------------
extern "C" void kernel_launch(void* const* d_in, const int* in_sizes, int n_in,
                              void* d_out, int out_size) {
    const float* x        = (const float*)d_in[0];
    const float* W1       = (const float*)d_in[1];
    const float* att_src1 = (const float*)d_in[2];
    const float* att_dst1 = (const float*)d_in[3];
    const float* b1       = (const float*)d_in[4];
    const float* W2       = (const float*)d_in[5];
    const float* att_src2 = (const float*)d_in[6];
    const float* att_dst2 = (const float*)d_in[7];
    const float* b2       = (const float*)d_in[8];
    const float* Wfc      = (const float*)d_in[9];
    const float* bfc      = (const float*)d_in[10];
    const void*  ei       = d_in[11];
    const void*  batch    = d_in[12];
    float* out = (float*)d_out;

    const int T = 256;
    int nb_nodes = (N_NODES + T - 1) / T;     // 391
    k_misc<<<nb_nodes, T>>>((const int*)ei, (const int*)batch, W1, att_src1, att_dst1);
    k_hist<<<(E_TOT + T - 1) / T, T>>>(ei, batch);
    k_scan1<<<N_SBLK, SCAN_BLK>>>();
    k_scan3<<<nb_nodes, T>>>();
    k_scatter<<<(E_TOT + T - 1) / T, T>>>(ei);

    k_l1<<<(N_NODES * 32 + T - 1) / T, T>>>(x);
    k_gemm2<<<N_NODES / 16, 128>>>(W1, b1, W2, att_src2, att_dst2);
    k_l2<<<(N_NODES * 32 + T - 1) / T, T>>>();
    k_final<<<1, 64>>>(b2, Wfc, bfc, out);
}

// round 10
// speedup vs baseline: 2.2903x; 1.8965x over previous
#include <cuda_runtime.h>
#include <cuda_bf16.h>

#define N_NODES 100000
#define N_EDGES 1600000
#define E_TOT   (N_EDGES + N_NODES)
#define N_GRAPHS 64
#define NEG_SLOPE 0.2f
#define NEG_BIG  -1e30f
#define SCAN_BLK 1024
#define N_SBLK   ((N_NODES + SCAN_BLK - 1) / SCAN_BLK)   // 98
#define CAP1     100     // layer-1 per-warp slot capacity
#define CAP2     64      // layer-2 per-warp slot capacity
#define SWS      68      // padded head stride for s_w (bank-conflict-free)

// ---------------- scratch (device globals; no allocation) ----------------
__device__ float    g_s1[8], g_d1[8];
__device__ int      g_ei_is64, g_b_is64;
__device__ int      g_batch[N_NODES];
__device__ int      g_deg[N_NODES];
__device__ int      g_incl[N_NODES];
__device__ int      g_bsum[N_SBLK];
__device__ int      g_rowstart[N_NODES + 1];
__device__ int      g_cursor[N_NODES];
__device__ int      g_csr_src[E_TOT];
__device__ float    g_t1  [N_NODES * 8];
__device__ __nv_bfloat162 g_h2b[N_NODES * 64];   // h2 in bf16 (message values)
__device__ float    g_as2 [N_NODES * 8];
__device__ float    g_ad2 [N_NODES * 8];
__device__ float    g_pool[N_NODES * 16];        // per-node pooled head-mean

__device__ __forceinline__ float lrelu(float v) {
    return v > 0.f ? v : NEG_SLOPE * v;
}

// packed f32x2 helpers
__device__ __forceinline__ unsigned long long pack2(float lo, float hi) {
    unsigned long long r;
    asm("mov.b64 %0, {%1, %2};" : "=l"(r) : "f"(lo), "f"(hi));
    return r;
}
__device__ __forceinline__ void unpack2(unsigned long long p, float& lo, float& hi) {
    asm("mov.b64 {%0, %1}, %2;" : "=f"(lo), "=f"(hi) : "l"(p));
}
__device__ __forceinline__ void ffma2(unsigned long long& acc,
                                      unsigned long long a,
                                      unsigned long long b) {
    asm("fma.rn.f32x2 %0, %1, %2, %0;" : "+l"(acc) : "l"(a), "l"(b));
}

__device__ __forceinline__ void acc_bf16(const uint2 v, float w,
                                         float& ax, float& ay, float& az, float& aw) {
    __nv_bfloat162 b0 = *reinterpret_cast<const __nv_bfloat162*>(&v.x);
    __nv_bfloat162 b1 = *reinterpret_cast<const __nv_bfloat162*>(&v.y);
    float2 f0 = __bfloat1622float2(b0);
    float2 f1 = __bfloat1622float2(b1);
    ax = fmaf(w, f0.x, ax);
    ay = fmaf(w, f0.y, ay);
    az = fmaf(w, f1.x, az);
    aw = fmaf(w, f1.y, aw);
}

// ---------------- setup ----------------

// multi-block: zero deg; block 0 also detects dtypes + preps s1/d1
__global__ void k_misc(const int* __restrict__ ei,
                       const int* __restrict__ ba,
                       const float* __restrict__ W1,
                       const float* __restrict__ att_src1,
                       const float* __restrict__ att_dst1) {
    int i = blockIdx.x * blockDim.x + threadIdx.x;
    if (i < N_NODES) g_deg[i] = 0;
    if (blockIdx.x == 0) {
        __shared__ int s_e, s_b;
        int t = threadIdx.x;
        if (t == 0) { s_e = 1; s_b = 1; }
        __syncthreads();
        if (t < 64) {
            int we = 2 * (t * 24999 + 13) + 1;      // < 3,200,000
            if (ei[we] != 0) atomicExch(&s_e, 0);
            int wb = (N_NODES - 1) - 2 * t;         // odd, in-bounds
            if (ba[wb] != 0) atomicExch(&s_b, 0);
        }
        __syncthreads();
        if (t == 0) {
            g_ei_is64 = s_e;
            g_b_is64  = s_b;
            g_rowstart[N_NODES] = E_TOT;
        }
        if (t < 8) {
            float a = 0.f, b = 0.f;
            for (int c = 0; c < 8; c++) {
                a += W1[t * 8 + c] * att_src1[t * 8 + c];
                b += W1[t * 8 + c] * att_dst1[t * 8 + c];
            }
            g_s1[t] = a;
            g_d1[t] = b;
        }
    }
}

__global__ void k_hist(const void* __restrict__ eiv,
                       const void* __restrict__ bav) {
    int i = blockIdx.x * blockDim.x + threadIdx.x;
    if (i < E_TOT) {
        int d;
        if (i < N_EDGES) {
            d = g_ei_is64 ? (int)((const long long*)eiv)[N_EDGES + i]
                          : ((const int*)eiv)[N_EDGES + i];
        } else {
            d = i - N_EDGES;
        }
        atomicAdd(&g_deg[d], 1);
    }
    if (i < N_NODES) {
        g_batch[i] = g_b_is64 ? (int)((const long long*)bav)[i]
                              : ((const int*)bav)[i];
    }
}

// stage 1: per-block inclusive scan + block sums
__global__ void k_scan1() {
    __shared__ int sh[SCAN_BLK];
    int t = threadIdx.x;
    int i = blockIdx.x * SCAN_BLK + t;
    int v = (i < N_NODES) ? g_deg[i] : 0;
    sh[t] = v;
    __syncthreads();
#pragma unroll
    for (int off = 1; off < SCAN_BLK; off <<= 1) {
        int tmp = (t >= off) ? sh[t - off] : 0;
        __syncthreads();
        sh[t] += tmp;
        __syncthreads();
    }
    if (i < N_NODES) g_incl[i] = sh[t];
    if (t == SCAN_BLK - 1) g_bsum[blockIdx.x] = sh[t];
}

// stage 2 (fused): each 256-thread block computes its scan1-block prefix itself
__global__ void k_scan3() {
    __shared__ int s_boff;
    if (threadIdx.x < 32) {
        int sb = blockIdx.x >> 2;    // scan1 block index (1024/256)
        int acc = 0;
        for (int j = threadIdx.x; j < sb; j += 32) acc += g_bsum[j];
#pragma unroll
        for (int off = 16; off >= 1; off >>= 1)
            acc += __shfl_xor_sync(0xffffffffu, acc, off);
        if (threadIdx.x == 0) s_boff = acc;
    }
    __syncthreads();
    int i = blockIdx.x * blockDim.x + threadIdx.x;
    if (i >= N_NODES) return;
    int rs = g_incl[i] - g_deg[i] + s_boff;
    g_rowstart[i] = rs;
    g_cursor[i]   = rs;
}

__global__ void k_scatter(const void* __restrict__ eiv) {
    int i = blockIdx.x * blockDim.x + threadIdx.x;
    if (i >= E_TOT) return;
    int s, d;
    if (i < N_EDGES) {
        if (g_ei_is64) {
            const long long* ei = (const long long*)eiv;
            s = (int)ei[i];
            d = (int)ei[N_EDGES + i];
        } else {
            const int* ei = (const int*)eiv;
            s = ei[i];
            d = ei[N_EDGES + i];
        }
    } else {
        s = i - N_EDGES;
        d = s;
    }
    int p = atomicAdd(&g_cursor[d], 1);
    g_csr_src[p] = s;
}

// ---- layer 1: warp per dst node, smem-staged xs, no-max softmax ----
// |logit| <= |x|max*(|s1|+|d1|) ~ 15, so raw __expf is fp32-safe.
__global__ void __launch_bounds__(256) k_l1(const float* __restrict__ x) {
    __shared__ float s_x[8][CAP1];
    int w = (blockIdx.x * blockDim.x + threadIdx.x) >> 5;
    if (w >= N_NODES) return;
    int wl = (threadIdx.x >> 5);
    int lane = threadIdx.x & 31;
    int eo = lane >> 3, h = lane & 7;
    int start = g_rowstart[w], end = g_rowstart[w + 1];
    int deg = end - start;
    float cs = g_s1[h];
    float cd = g_d1[h] * x[w];

    if (deg <= CAP1) {
        for (int j = lane; j < deg; j += 32)
            s_x[wl][j] = x[g_csr_src[start + j]];
        __syncwarp();
        float den = 0.f, num = 0.f;
        for (int i = eo; i < deg; i += 4) {
            float xs = s_x[wl][i];
            float wj = __expf(lrelu(fmaf(xs, cs, cd)));
            den += wj;
            num += wj * xs;
        }
#pragma unroll
        for (int off = 8; off <= 16; off <<= 1) {
            den += __shfl_xor_sync(0xffffffffu, den, off);
            num += __shfl_xor_sync(0xffffffffu, num, off);
        }
        if (lane < 8) g_t1[w * 8 + h] = num / den;
    } else {
        // fallback: online softmax with max tracking (statistically never)
        float m = NEG_BIG, den = 0.f, num = 0.f;
        for (int j = start + eo; j < end; j += 4) {
            float xs = x[g_csr_src[j]];
            float e = lrelu(fmaf(xs, cs, cd));
            float nm = fmaxf(m, e);
            float r = __expf(m - nm);
            float wj = __expf(e - nm);
            den = den * r + wj;
            num = num * r + wj * xs;
            m = nm;
        }
#pragma unroll
        for (int off = 8; off <= 16; off <<= 1) {
            float m2 = __shfl_xor_sync(0xffffffffu, m,   off);
            float d2 = __shfl_xor_sync(0xffffffffu, den, off);
            float n2 = __shfl_xor_sync(0xffffffffu, num, off);
            float nm = fmaxf(m, m2);
            float r1 = __expf(m - nm), r2 = __expf(m2 - nm);
            den = den * r1 + d2 * r2;
            num = num * r1 + n2 * r2;
            m = nm;
        }
        if (lane < 8) g_t1[w * 8 + h] = num / den;
    }
}

// ---- GEMM2 + fused elu input + fused att2 epilogue; h2 stored bf16 ----
__global__ void __launch_bounds__(128) k_gemm2(const float* __restrict__ W1,
                                               const float* __restrict__ b1,
                                               const float* __restrict__ W2,
                                               const float* __restrict__ att_src2,
                                               const float* __restrict__ att_dst2) {
    __shared__ float s_in[16][64];
    int t = threadIdx.x;
    int n0 = blockIdx.x * 16;
    for (int e = t; e < 1024; e += 128) {
        int nn = e >> 6, j = e & 63;
        float v = fmaf(g_t1[(n0 + nn) * 8 + (j >> 3)], W1[j], b1[j]);
        s_in[nn][j] = v > 0.f ? v : (__expf(v) - 1.f);
    }
    __syncthreads();
    int lane = t & 31;
    int ng = t >> 5;
    int c = lane * 4;
    int h = lane >> 2;
    unsigned long long acc01[4], acc23[4];
#pragma unroll
    for (int i = 0; i < 4; i++) { acc01[i] = 0ull; acc23[i] = 0ull; }
    const float* w2p = &W2[c];
#pragma unroll 4
    for (int k = 0; k < 64; k++) {
        float4 wv = *reinterpret_cast<const float4*>(w2p + k * 128);
        unsigned long long s01 = pack2(s_in[ng * 4 + 0][k], s_in[ng * 4 + 1][k]);
        unsigned long long s23 = pack2(s_in[ng * 4 + 2][k], s_in[ng * 4 + 3][k]);
        unsigned long long w0 = pack2(wv.x, wv.x);
        unsigned long long w1 = pack2(wv.y, wv.y);
        unsigned long long w2 = pack2(wv.z, wv.z);
        unsigned long long w3 = pack2(wv.w, wv.w);
        ffma2(acc01[0], w0, s01); ffma2(acc23[0], w0, s23);
        ffma2(acc01[1], w1, s01); ffma2(acc23[1], w1, s23);
        ffma2(acc01[2], w2, s01); ffma2(acc23[2], w2, s23);
        ffma2(acc01[3], w3, s01); ffma2(acc23[3], w3, s23);
    }
    float4 av = *reinterpret_cast<const float4*>(&att_src2[c]);
    float4 dv = *reinterpret_cast<const float4*>(&att_dst2[c]);
    float4 row[4];
    {
        float lo[4], hi[4];
#pragma unroll
        for (int i = 0; i < 4; i++) unpack2(acc01[i], lo[i], hi[i]);
        row[0] = make_float4(lo[0], lo[1], lo[2], lo[3]);
        row[1] = make_float4(hi[0], hi[1], hi[2], hi[3]);
#pragma unroll
        for (int i = 0; i < 4; i++) unpack2(acc23[i], lo[i], hi[i]);
        row[2] = make_float4(lo[0], lo[1], lo[2], lo[3]);
        row[3] = make_float4(hi[0], hi[1], hi[2], hi[3]);
    }
    int nb = n0 + ng * 4;
#pragma unroll
    for (int r = 0; r < 4; r++) {
        __nv_bfloat162 b0 = __float22bfloat162_rn(make_float2(row[r].x, row[r].y));
        __nv_bfloat162 b1v = __float22bfloat162_rn(make_float2(row[r].z, row[r].w));
        uint2 packed;
        packed.x = *reinterpret_cast<unsigned*>(&b0);
        packed.y = *reinterpret_cast<unsigned*>(&b1v);
        *reinterpret_cast<uint2*>(&g_h2b[(nb + r) * 64 + lane * 2]) = packed;
        float pa = row[r].x * av.x + row[r].y * av.y + row[r].z * av.z + row[r].w * av.w;
        float pd = row[r].x * dv.x + row[r].y * dv.y + row[r].z * dv.z + row[r].w * dv.w;
        pa += __shfl_xor_sync(0xffffffffu, pa, 1);
        pd += __shfl_xor_sync(0xffffffffu, pd, 1);
        pa += __shfl_xor_sync(0xffffffffu, pa, 2);
        pd += __shfl_xor_sync(0xffffffffu, pd, 2);
        if ((lane & 3) == 0) {
            g_as2[(nb + r) * 8 + h] = pa;
            g_ad2[(nb + r) * 8 + h] = pd;
        }
    }
}

// ---- layer 2 fused: smem-staged weights + src, bf16 gather; plain stores ----
__global__ void __launch_bounds__(256) k_l2() {
    __shared__ float s_w[8][8 * SWS];  // [warp][h*SWS + slot]
    __shared__ int   s_s[8][CAP2];     // [warp][slot]
    int d = (blockIdx.x * blockDim.x + threadIdx.x) >> 5;
    if (d >= N_NODES) return;
    int wl = threadIdx.x >> 5;
    int lane = threadIdx.x & 31;
    int start = g_rowstart[d];
    int deg = g_rowstart[d + 1] - start;
    int h = lane & 7, eo = lane >> 3;
    float ad = g_ad2[d * 8 + h];

    float ax = 0.f, ay = 0.f, az = 0.f, aw = 0.f;
    int hh = lane >> 2;
    float dh;

    if (deg <= CAP2) {
        for (int j = lane; j < deg; j += 32)
            s_s[wl][j] = g_csr_src[start + j];
        __syncwarp();
        float m = NEG_BIG;
        for (int i = eo; i < deg; i += 4) {
            int s = s_s[wl][i];
            float e = lrelu(g_as2[s * 8 + h] + ad);
            s_w[wl][h * SWS + i] = e;
            m = fmaxf(m, e);
        }
#pragma unroll
        for (int off = 8; off <= 16; off <<= 1)
            m = fmaxf(m, __shfl_xor_sync(0xffffffffu, m, off));
        __syncwarp();
        float den = 0.f;
        for (int i = eo; i < deg; i += 4) {
            float wgt = __expf(s_w[wl][h * SWS + i] - m);
            s_w[wl][h * SWS + i] = wgt;
            den += wgt;
        }
#pragma unroll
        for (int off = 8; off <= 16; off <<= 1)
            den += __shfl_xor_sync(0xffffffffu, den, off);
        dh = __shfl_sync(0xffffffffu, den, hh);
        __syncwarp();
        const float* wrow = &s_w[wl][hh * SWS];
        int k = 0;
        for (; k + 3 < deg; k += 4) {
            int s0 = s_s[wl][k], s1 = s_s[wl][k + 1];
            int s2 = s_s[wl][k + 2], s3 = s_s[wl][k + 3];
            float w0 = wrow[k], w1 = wrow[k + 1];
            float w2 = wrow[k + 2], w3 = wrow[k + 3];
            uint2 v0 = *reinterpret_cast<const uint2*>(&g_h2b[s0 * 64 + lane * 2]);
            uint2 v1 = *reinterpret_cast<const uint2*>(&g_h2b[s1 * 64 + lane * 2]);
            uint2 v2 = *reinterpret_cast<const uint2*>(&g_h2b[s2 * 64 + lane * 2]);
            uint2 v3 = *reinterpret_cast<const uint2*>(&g_h2b[s3 * 64 + lane * 2]);
            acc_bf16(v0, w0, ax, ay, az, aw);
            acc_bf16(v1, w1, ax, ay, az, aw);
            acc_bf16(v2, w2, ax, ay, az, aw);
            acc_bf16(v3, w3, ax, ay, az, aw);
        }
        for (; k < deg; k++) {
            int s0 = s_s[wl][k];
            float w0 = wrow[k];
            uint2 v0 = *reinterpret_cast<const uint2*>(&g_h2b[s0 * 64 + lane * 2]);
            acc_bf16(v0, w0, ax, ay, az, aw);
        }
    } else {
        // fallback (statistically never)
        float m = NEG_BIG, den = 0.f;
        for (int j = start + eo; j < start + deg; j += 4) {
            int s = g_csr_src[j];
            float e = lrelu(g_as2[s * 8 + h] + ad);
            float nm = fmaxf(m, e);
            den = den * __expf(m - nm) + __expf(e - nm);
            m = nm;
        }
#pragma unroll
        for (int off = 8; off <= 16; off <<= 1) {
            float m2 = __shfl_xor_sync(0xffffffffu, m,   off);
            float d2 = __shfl_xor_sync(0xffffffffu, den, off);
            float nm = fmaxf(m, m2);
            den = den * __expf(m - nm) + d2 * __expf(m2 - nm);
            m = nm;
        }
        float mh  = __shfl_sync(0xffffffffu, m,   hh);
        dh        = __shfl_sync(0xffffffffu, den, hh);
        float adh = __shfl_sync(0xffffffffu, ad,  hh);
        for (int j = start; j < start + deg; j++) {
            int s0 = g_csr_src[j];
            float w0 = __expf(lrelu(g_as2[s0 * 8 + hh] + adh) - mh);
            uint2 v0 = *reinterpret_cast<const uint2*>(&g_h2b[s0 * 64 + lane * 2]);
            acc_bf16(v0, w0, ax, ay, az, aw);
        }
    }

    float inv = 0.125f / dh;
    ax *= inv; ay *= inv; az *= inv; aw *= inv;
#pragma unroll
    for (int off = 4; off <= 16; off <<= 1) {
        ax += __shfl_xor_sync(0xffffffffu, ax, off);
        ay += __shfl_xor_sync(0xffffffffu, ay, off);
        az += __shfl_xor_sync(0xffffffffu, az, off);
        aw += __shfl_xor_sync(0xffffffffu, aw, off);
    }
    // plain per-node store — zero contended atomics
    if (lane < 4)
        *reinterpret_cast<float4*>(&g_pool[d * 16 + lane * 4]) =
            make_float4(ax, ay, az, aw);
}

// one block per graph: sum contiguous node range of g_pool, then FC
__global__ void __launch_bounds__(256) k_final(const float* __restrict__ b2,
                                               const float* __restrict__ Wfc,
                                               const float* __restrict__ bfc,
                                               float* __restrict__ out) {
    __shared__ float s_part[8][16];
    __shared__ float s_pool[16];
    int g = blockIdx.x;
    int t = threadIdx.x;
    // range of nodes for graph g (batch sorted)
    int lo = 0, hi = N_NODES;
    while (lo < hi) {
        int mid = (lo + hi) >> 1;
        if (g_batch[mid] < g) lo = mid + 1; else hi = mid;
    }
    int lb = lo;
    lo = 0; hi = N_NODES;
    while (lo < hi) {
        int mid = (lo + hi) >> 1;
        if (g_batch[mid] < g + 1) lo = mid + 1; else hi = mid;
    }
    int ub = lo;
    // thread t: channel c = t & 15, node stride 16
    int c = t & 15;
    float acc = 0.f;
    for (int n = lb + (t >> 4); n < ub; n += 16)
        acc += g_pool[n * 16 + c];
    // warp-level: lanes c and c+16 hold same channel
    acc += __shfl_xor_sync(0xffffffffu, acc, 16);
    int wid = t >> 5, lane = t & 31;
    if (lane < 16) s_part[wid][lane] = acc;
    __syncthreads();
    if (t < 16) {
        float v = 0.f;
#pragma unroll
        for (int wds = 0; wds < 8; wds++) v += s_part[wds][t];
        float cnt = (float)(ub - lb);
        s_pool[t] = v / fmaxf(cnt, 1.f) + b2[t];
    }
    __syncthreads();
    if (t < 4) {
        float r = bfc[t];
#pragma unroll
        for (int cc = 0; cc < 16; cc++) r += s_pool[cc] * Wfc[cc * 4 + t];
        out[g * 4 + t] = r;
    }
}

// ---------------- launch ----------------
extern "C" void kernel_launch(void* const* d_in, const int* in_sizes, int n_in,
                              void* d_out, int out_size) {
    const float* x        = (const float*)d_in[0];
    const float* W1       = (const float*)d_in[1];
    const float* att_src1 = (const float*)d_in[2];
    const float* att_dst1 = (const float*)d_in[3];
    const float* b1       = (const float*)d_in[4];
    const float* W2       = (const float*)d_in[5];
    const float* att_src2 = (const float*)d_in[6];
    const float* att_dst2 = (const float*)d_in[7];
    const float* b2       = (const float*)d_in[8];
    const float* Wfc      = (const float*)d_in[9];
    const float* bfc      = (const float*)d_in[10];
    const void*  ei       = d_in[11];
    const void*  batch    = d_in[12];
    float* out = (float*)d_out;

    const int T = 256;
    int nb_nodes = (N_NODES + T - 1) / T;     // 391
    k_misc<<<nb_nodes, T>>>((const int*)ei, (const int*)batch, W1, att_src1, att_dst1);
    k_hist<<<(E_TOT + T - 1) / T, T>>>(ei, batch);
    k_scan1<<<N_SBLK, SCAN_BLK>>>();
    k_scan3<<<nb_nodes, T>>>();
    k_scatter<<<(E_TOT + T - 1) / T, T>>>(ei);

    k_l1<<<(N_NODES * 32 + T - 1) / T, T>>>(x);
    k_gemm2<<<N_NODES / 16, 128>>>(W1, b1, W2, att_src2, att_dst2);
    k_l2<<<(N_NODES * 32 + T - 1) / T, T>>>();
    k_final<<<N_GRAPHS, 256>>>(b2, Wfc, bfc, out);
}

// round 11
// speedup vs baseline: 2.4211x; 1.0571x over previous
#include <cuda_runtime.h>
#include <cuda_bf16.h>

#define N_NODES 100000
#define N_EDGES 1600000
#define E_TOT   (N_EDGES + N_NODES)
#define N_GRAPHS 64
#define NEG_SLOPE 0.2f
#define NEG_BIG  -1e30f
#define SCAN_BLK 1024
#define N_SBLK   ((N_NODES + SCAN_BLK - 1) / SCAN_BLK)   // 98
#define CAP1     100     // layer-1 per-warp slot capacity

// ---------------- scratch (device globals; no allocation) ----------------
__device__ float    g_s1[8], g_d1[8];
__device__ int      g_ei_is64, g_b_is64;
__device__ int      g_batch[N_NODES];
__device__ int      g_deg[N_NODES];
__device__ int      g_incl[N_NODES];
__device__ int      g_bsum[N_SBLK];
__device__ int      g_rowstart[N_NODES + 1];
__device__ int      g_cursor[N_NODES];
__device__ int      g_csr_src[E_TOT];
__device__ float    g_t1  [N_NODES * 8];
__device__ __nv_bfloat162 g_h2b[N_NODES * 64];   // h2 in bf16 (message values)
__device__ float    g_as2 [N_NODES * 8];
__device__ float    g_ad2 [N_NODES * 8];
__device__ float    g_pool[N_NODES * 16];        // per-node pooled head-mean

__device__ __forceinline__ float lrelu(float v) {
    return v > 0.f ? v : NEG_SLOPE * v;
}

// packed f32x2 helpers
__device__ __forceinline__ unsigned long long pack2(float lo, float hi) {
    unsigned long long r;
    asm("mov.b64 %0, {%1, %2};" : "=l"(r) : "f"(lo), "f"(hi));
    return r;
}
__device__ __forceinline__ void unpack2(unsigned long long p, float& lo, float& hi) {
    asm("mov.b64 {%0, %1}, %2;" : "=f"(lo), "=f"(hi) : "l"(p));
}
__device__ __forceinline__ void ffma2(unsigned long long& acc,
                                      unsigned long long a,
                                      unsigned long long b) {
    asm("fma.rn.f32x2 %0, %1, %2, %0;" : "+l"(acc) : "l"(a), "l"(b));
}

// accumulate 8 bf16 channels (one uint4) with weight w
__device__ __forceinline__ void acc8(const uint4 v, float w, float* a) {
    float2 f;
    f = __bfloat1622float2(*reinterpret_cast<const __nv_bfloat162*>(&v.x));
    a[0] = fmaf(w, f.x, a[0]); a[1] = fmaf(w, f.y, a[1]);
    f = __bfloat1622float2(*reinterpret_cast<const __nv_bfloat162*>(&v.y));
    a[2] = fmaf(w, f.x, a[2]); a[3] = fmaf(w, f.y, a[3]);
    f = __bfloat1622float2(*reinterpret_cast<const __nv_bfloat162*>(&v.z));
    a[4] = fmaf(w, f.x, a[4]); a[5] = fmaf(w, f.y, a[5]);
    f = __bfloat1622float2(*reinterpret_cast<const __nv_bfloat162*>(&v.w));
    a[6] = fmaf(w, f.x, a[6]); a[7] = fmaf(w, f.y, a[7]);
}

// ---------------- setup ----------------

// multi-block: zero deg; block 0 also detects dtypes + preps s1/d1
__global__ void k_misc(const int* __restrict__ ei,
                       const int* __restrict__ ba,
                       const float* __restrict__ W1,
                       const float* __restrict__ att_src1,
                       const float* __restrict__ att_dst1) {
    int i = blockIdx.x * blockDim.x + threadIdx.x;
    if (i < N_NODES) g_deg[i] = 0;
    if (blockIdx.x == 0) {
        __shared__ int s_e, s_b;
        int t = threadIdx.x;
        if (t == 0) { s_e = 1; s_b = 1; }
        __syncthreads();
        if (t < 64) {
            int we = 2 * (t * 24999 + 13) + 1;      // < 3,200,000
            if (ei[we] != 0) atomicExch(&s_e, 0);
            int wb = (N_NODES - 1) - 2 * t;         // odd, in-bounds
            if (ba[wb] != 0) atomicExch(&s_b, 0);
        }
        __syncthreads();
        if (t == 0) {
            g_ei_is64 = s_e;
            g_b_is64  = s_b;
            g_rowstart[N_NODES] = E_TOT;
        }
        if (t < 8) {
            float a = 0.f, b = 0.f;
            for (int c = 0; c < 8; c++) {
                a += W1[t * 8 + c] * att_src1[t * 8 + c];
                b += W1[t * 8 + c] * att_dst1[t * 8 + c];
            }
            g_s1[t] = a;
            g_d1[t] = b;
        }
    }
}

__global__ void k_hist(const void* __restrict__ eiv,
                       const void* __restrict__ bav) {
    int i = blockIdx.x * blockDim.x + threadIdx.x;
    if (i < E_TOT) {
        int d;
        if (i < N_EDGES) {
            d = g_ei_is64 ? (int)((const long long*)eiv)[N_EDGES + i]
                          : ((const int*)eiv)[N_EDGES + i];
        } else {
            d = i - N_EDGES;
        }
        atomicAdd(&g_deg[d], 1);
    }
    if (i < N_NODES) {
        g_batch[i] = g_b_is64 ? (int)((const long long*)bav)[i]
                              : ((const int*)bav)[i];
    }
}

// stage 1: per-block inclusive scan + block sums
__global__ void k_scan1() {
    __shared__ int sh[SCAN_BLK];
    int t = threadIdx.x;
    int i = blockIdx.x * SCAN_BLK + t;
    int v = (i < N_NODES) ? g_deg[i] : 0;
    sh[t] = v;
    __syncthreads();
#pragma unroll
    for (int off = 1; off < SCAN_BLK; off <<= 1) {
        int tmp = (t >= off) ? sh[t - off] : 0;
        __syncthreads();
        sh[t] += tmp;
        __syncthreads();
    }
    if (i < N_NODES) g_incl[i] = sh[t];
    if (t == SCAN_BLK - 1) g_bsum[blockIdx.x] = sh[t];
}

// stage 2 (fused): each 256-thread block computes its scan1-block prefix itself
__global__ void k_scan3() {
    __shared__ int s_boff;
    if (threadIdx.x < 32) {
        int sb = blockIdx.x >> 2;    // scan1 block index (1024/256)
        int acc = 0;
        for (int j = threadIdx.x; j < sb; j += 32) acc += g_bsum[j];
#pragma unroll
        for (int off = 16; off >= 1; off >>= 1)
            acc += __shfl_xor_sync(0xffffffffu, acc, off);
        if (threadIdx.x == 0) s_boff = acc;
    }
    __syncthreads();
    int i = blockIdx.x * blockDim.x + threadIdx.x;
    if (i >= N_NODES) return;
    int rs = g_incl[i] - g_deg[i] + s_boff;
    g_rowstart[i] = rs;
    g_cursor[i]   = rs;
}

__global__ void k_scatter(const void* __restrict__ eiv) {
    int i = blockIdx.x * blockDim.x + threadIdx.x;
    if (i >= E_TOT) return;
    int s, d;
    if (i < N_EDGES) {
        if (g_ei_is64) {
            const long long* ei = (const long long*)eiv;
            s = (int)ei[i];
            d = (int)ei[N_EDGES + i];
        } else {
            const int* ei = (const int*)eiv;
            s = ei[i];
            d = ei[N_EDGES + i];
        }
    } else {
        s = i - N_EDGES;
        d = s;
    }
    int p = atomicAdd(&g_cursor[d], 1);
    g_csr_src[p] = s;
}

// ---- layer 1: warp per dst node, smem-staged xs, no-max softmax ----
// |logit| <= |x|max*(|s1|+|d1|) ~ 15, so raw __expf is fp32-safe.
__global__ void __launch_bounds__(256) k_l1(const float* __restrict__ x) {
    __shared__ float s_x[8][CAP1];
    int w = (blockIdx.x * blockDim.x + threadIdx.x) >> 5;
    if (w >= N_NODES) return;
    int wl = (threadIdx.x >> 5);
    int lane = threadIdx.x & 31;
    int eo = lane >> 3, h = lane & 7;
    int start = g_rowstart[w], end = g_rowstart[w + 1];
    int deg = end - start;
    float cs = g_s1[h];
    float cd = g_d1[h] * x[w];

    if (deg <= CAP1) {
        for (int j = lane; j < deg; j += 32)
            s_x[wl][j] = x[g_csr_src[start + j]];
        __syncwarp();
        float den = 0.f, num = 0.f;
        for (int i = eo; i < deg; i += 4) {
            float xs = s_x[wl][i];
            float wj = __expf(lrelu(fmaf(xs, cs, cd)));
            den += wj;
            num += wj * xs;
        }
#pragma unroll
        for (int off = 8; off <= 16; off <<= 1) {
            den += __shfl_xor_sync(0xffffffffu, den, off);
            num += __shfl_xor_sync(0xffffffffu, num, off);
        }
        if (lane < 8) g_t1[w * 8 + h] = num / den;
    } else {
        // fallback: direct gather, no staging (statistically never)
        float den = 0.f, num = 0.f;
        for (int j = start + eo; j < end; j += 4) {
            float xs = x[g_csr_src[j]];
            float wj = __expf(fminf(lrelu(fmaf(xs, cs, cd)), 60.f));
            den += wj;
            num += wj * xs;
        }
#pragma unroll
        for (int off = 8; off <= 16; off <<= 1) {
            den += __shfl_xor_sync(0xffffffffu, den, off);
            num += __shfl_xor_sync(0xffffffffu, num, off);
        }
        if (lane < 8) g_t1[w * 8 + h] = num / den;
    }
}

// ---- GEMM2 + fused elu input + fused att2 epilogue; h2 stored bf16 ----
__global__ void __launch_bounds__(128) k_gemm2(const float* __restrict__ W1,
                                               const float* __restrict__ b1,
                                               const float* __restrict__ W2,
                                               const float* __restrict__ att_src2,
                                               const float* __restrict__ att_dst2) {
    __shared__ float s_in[16][64];
    int t = threadIdx.x;
    int n0 = blockIdx.x * 16;
    for (int e = t; e < 1024; e += 128) {
        int nn = e >> 6, j = e & 63;
        float v = fmaf(g_t1[(n0 + nn) * 8 + (j >> 3)], W1[j], b1[j]);
        s_in[nn][j] = v > 0.f ? v : (__expf(v) - 1.f);
    }
    __syncthreads();
    int lane = t & 31;
    int ng = t >> 5;
    int c = lane * 4;
    int h = lane >> 2;
    unsigned long long acc01[4], acc23[4];
#pragma unroll
    for (int i = 0; i < 4; i++) { acc01[i] = 0ull; acc23[i] = 0ull; }
    const float* w2p = &W2[c];
#pragma unroll 4
    for (int k = 0; k < 64; k++) {
        float4 wv = *reinterpret_cast<const float4*>(w2p + k * 128);
        unsigned long long s01 = pack2(s_in[ng * 4 + 0][k], s_in[ng * 4 + 1][k]);
        unsigned long long s23 = pack2(s_in[ng * 4 + 2][k], s_in[ng * 4 + 3][k]);
        unsigned long long w0 = pack2(wv.x, wv.x);
        unsigned long long w1 = pack2(wv.y, wv.y);
        unsigned long long w2 = pack2(wv.z, wv.z);
        unsigned long long w3 = pack2(wv.w, wv.w);
        ffma2(acc01[0], w0, s01); ffma2(acc23[0], w0, s23);
        ffma2(acc01[1], w1, s01); ffma2(acc23[1], w1, s23);
        ffma2(acc01[2], w2, s01); ffma2(acc23[2], w2, s23);
        ffma2(acc01[3], w3, s01); ffma2(acc23[3], w3, s23);
    }
    float4 av = *reinterpret_cast<const float4*>(&att_src2[c]);
    float4 dv = *reinterpret_cast<const float4*>(&att_dst2[c]);
    float4 row[4];
    {
        float lo[4], hi[4];
#pragma unroll
        for (int i = 0; i < 4; i++) unpack2(acc01[i], lo[i], hi[i]);
        row[0] = make_float4(lo[0], lo[1], lo[2], lo[3]);
        row[1] = make_float4(hi[0], hi[1], hi[2], hi[3]);
#pragma unroll
        for (int i = 0; i < 4; i++) unpack2(acc23[i], lo[i], hi[i]);
        row[2] = make_float4(lo[0], lo[1], lo[2], lo[3]);
        row[3] = make_float4(hi[0], hi[1], hi[2], hi[3]);
    }
    int nb = n0 + ng * 4;
#pragma unroll
    for (int r = 0; r < 4; r++) {
        __nv_bfloat162 b0 = __float22bfloat162_rn(make_float2(row[r].x, row[r].y));
        __nv_bfloat162 b1v = __float22bfloat162_rn(make_float2(row[r].z, row[r].w));
        uint2 packed;
        packed.x = *reinterpret_cast<unsigned*>(&b0);
        packed.y = *reinterpret_cast<unsigned*>(&b1v);
        *reinterpret_cast<uint2*>(&g_h2b[(nb + r) * 64 + lane * 2]) = packed;
        float pa = row[r].x * av.x + row[r].y * av.y + row[r].z * av.z + row[r].w * av.w;
        float pd = row[r].x * dv.x + row[r].y * dv.y + row[r].z * dv.z + row[r].w * dv.w;
        pa += __shfl_xor_sync(0xffffffffu, pa, 1);
        pd += __shfl_xor_sync(0xffffffffu, pd, 1);
        pa += __shfl_xor_sync(0xffffffffu, pa, 2);
        pd += __shfl_xor_sync(0xffffffffu, pd, 2);
        if ((lane & 3) == 0) {
            g_as2[(nb + r) * 8 + h] = pa;
            g_ad2[(nb + r) * 8 + h] = pd;
        }
    }
}

// ---- layer 2: SINGLE PASS, zero smem. Warp = 1 dst node; 16 lanes per edge,
// 2 edges per iteration; unnormalized softmax accumulation (logits bounded,
// clamp@60 as overflow guard), divide by weight-sum at the end. ----
__global__ void __launch_bounds__(256) k_l2() {
    int d = (blockIdx.x * blockDim.x + threadIdx.x) >> 5;
    if (d >= N_NODES) return;
    int lane = threadIdx.x & 31;
    int start = g_rowstart[d];
    int deg = g_rowstart[d + 1] - start;
    int sub = lane >> 4;       // which edge of the pair
    int q   = lane & 15;       // channel chunk: channels q*8 .. q*8+7
    int h4  = q >> 1;          // head owning this chunk
    float ad4 = g_ad2[d * 8 + h4];
    const int* srcp = &g_csr_src[start];

    float acc[8];
#pragma unroll
    for (int r = 0; r < 8; r++) acc[r] = 0.f;
    float wsum = 0.f;

    int k = 0;
    for (; k + 4 <= deg; k += 4) {
        int s0 = srcp[k + sub];
        int s1 = srcp[k + 2 + sub];
        float e0 = lrelu(g_as2[s0 * 8 + h4] + ad4);
        float e1 = lrelu(g_as2[s1 * 8 + h4] + ad4);
        uint4 v0 = *reinterpret_cast<const uint4*>(&g_h2b[s0 * 64 + q * 4]);
        uint4 v1 = *reinterpret_cast<const uint4*>(&g_h2b[s1 * 64 + q * 4]);
        float w0 = __expf(fminf(e0, 60.f));
        float w1 = __expf(fminf(e1, 60.f));
        wsum += w0 + w1;
        acc8(v0, w0, acc);
        acc8(v1, w1, acc);
    }
    for (; k < deg; k += 2) {
        int idx = k + sub;
        bool valid = idx < deg;
        int s0 = srcp[valid ? idx : 0];
        float w0 = valid
            ? __expf(fminf(lrelu(g_as2[s0 * 8 + h4] + ad4), 60.f)) : 0.f;
        uint4 v0 = *reinterpret_cast<const uint4*>(&g_h2b[s0 * 64 + q * 4]);
        wsum += w0;
        acc8(v0, w0, acc);
    }

    // merge the two edge-halves (lane ^ 16)
    wsum += __shfl_xor_sync(0xffffffffu, wsum, 16);
#pragma unroll
    for (int r = 0; r < 8; r++)
        acc[r] += __shfl_xor_sync(0xffffffffu, acc[r], 16);
    // normalize + head-mean factor
    float inv = 0.125f / wsum;
#pragma unroll
    for (int r = 0; r < 8; r++) acc[r] *= inv;
    // head reduce: pooled[(q&1)*8 + r] = sum over q in {b, b+2, ..., b+14}
#pragma unroll
    for (int off = 2; off <= 8; off <<= 1) {
#pragma unroll
        for (int r = 0; r < 8; r++)
            acc[r] += __shfl_xor_sync(0xffffffffu, acc[r], off);
    }
    if (lane < 2) {
        float4* dst = reinterpret_cast<float4*>(&g_pool[d * 16 + lane * 8]);
        dst[0] = make_float4(acc[0], acc[1], acc[2], acc[3]);
        dst[1] = make_float4(acc[4], acc[5], acc[6], acc[7]);
    }
}

// one block per graph: sum contiguous node range of g_pool, then FC
__global__ void __launch_bounds__(256) k_final(const float* __restrict__ b2,
                                               const float* __restrict__ Wfc,
                                               const float* __restrict__ bfc,
                                               float* __restrict__ out) {
    __shared__ float s_part[8][16];
    __shared__ float s_pool[16];
    int g = blockIdx.x;
    int t = threadIdx.x;
    int lo = 0, hi = N_NODES;
    while (lo < hi) {
        int mid = (lo + hi) >> 1;
        if (g_batch[mid] < g) lo = mid + 1; else hi = mid;
    }
    int lb = lo;
    lo = 0; hi = N_NODES;
    while (lo < hi) {
        int mid = (lo + hi) >> 1;
        if (g_batch[mid] < g + 1) lo = mid + 1; else hi = mid;
    }
    int ub = lo;
    int c = t & 15;
    float acc = 0.f;
    for (int n = lb + (t >> 4); n < ub; n += 16)
        acc += g_pool[n * 16 + c];
    acc += __shfl_xor_sync(0xffffffffu, acc, 16);
    int wid = t >> 5, lane = t & 31;
    if (lane < 16) s_part[wid][lane] = acc;
    __syncthreads();
    if (t < 16) {
        float v = 0.f;
#pragma unroll
        for (int wds = 0; wds < 8; wds++) v += s_part[wds][t];
        float cnt = (float)(ub - lb);
        s_pool[t] = v / fmaxf(cnt, 1.f) + b2[t];
    }
    __syncthreads();
    if (t < 4) {
        float r = bfc[t];
#pragma unroll
        for (int cc = 0; cc < 16; cc++) r += s_pool[cc] * Wfc[cc * 4 + t];
        out[g * 4 + t] = r;
    }
}

// ---------------- launch ----------------
extern "C" void kernel_launch(void* const* d_in, const int* in_sizes, int n_in,
                              void* d_out, int out_size) {
    const float* x        = (const float*)d_in[0];
    const float* W1       = (const float*)d_in[1];
    const float* att_src1 = (const float*)d_in[2];
    const float* att_dst1 = (const float*)d_in[3];
    const float* b1       = (const float*)d_in[4];
    const float* W2       = (const float*)d_in[5];
    const float* att_src2 = (const float*)d_in[6];
    const float* att_dst2 = (const float*)d_in[7];
    const float* b2       = (const float*)d_in[8];
    const float* Wfc      = (const float*)d_in[9];
    const float* bfc      = (const float*)d_in[10];
    const void*  ei       = d_in[11];
    const void*  batch    = d_in[12];
    float* out = (float*)d_out;

    const int T = 256;
    int nb_nodes = (N_NODES + T - 1) / T;     // 391
    k_misc<<<nb_nodes, T>>>((const int*)ei, (const int*)batch, W1, att_src1, att_dst1);
    k_hist<<<(E_TOT + T - 1) / T, T>>>(ei, batch);
    k_scan1<<<N_SBLK, SCAN_BLK>>>();
    k_scan3<<<nb_nodes, T>>>();
    k_scatter<<<(E_TOT + T - 1) / T, T>>>(ei);

    k_l1<<<(N_NODES * 32 + T - 1) / T, T>>>(x);
    k_gemm2<<<N_NODES / 16, 128>>>(W1, b1, W2, att_src2, att_dst2);
    k_l2<<<(N_NODES * 32 + T - 1) / T, T>>>();
    k_final<<<N_GRAPHS, 256>>>(b2, Wfc, bfc, out);
}